// round 4
// baseline (speedup 1.0000x reference)
#include <cuda_runtime.h>
#include <cuda_fp16.h>

#define NN 50000
#define NE 800000
#define IND 128
#define HID 64
#define HEADS 4
#define C1 256            // HEADS*HID
#define EDIM 16

// ---------------- scratch (device globals) ----------------
__device__ uint4    g_h1h[NN * 32];         // [N,256] layer-1 feats, fp16 (512B/row)
__device__ float4   g_out1[NN * C1 / 4];    // layer-1 aggregate (normalized), fp32
__device__ __half2  g_h2h[NN * 32];         // [N,64] layer-2 feats, fp16 (128B/row)
__device__ float4   g_scr1[NE];             // per-edge exp(logit), 4 heads
__device__ float    g_ae2[NE];              // layer-2 edge-attr term
__device__ float4   g_asrc1[NN], g_adst1[NN];
__device__ float    g_asrc2[NN], g_adst2[NN];
__device__ float    g_v1[EDIM * HEADS];     // (We1 . ae1) collapsed
__device__ float    g_v2[EDIM];
// CSR
__device__ unsigned g_deg[NN];
__device__ unsigned g_cnt[NN];              // running insert ptr (init = ptr)
__device__ unsigned g_ptr[NN + 1];
__device__ int2     g_csr[NE];              // (edge_id, src)

// ---------------- helpers ----------------
__device__ __forceinline__ float lrelu(float x) { return x > 0.f ? x : 0.2f * x; }

__device__ __forceinline__ void fma2(unsigned long long& d,
                                     unsigned long long a, unsigned long long b) {
    asm("fma.rn.f32x2 %0, %1, %2, %0;" : "+l"(d) : "l"(a), "l"(b));
}
__device__ __forceinline__ unsigned long long pack2(float v) {
    unsigned long long r;
    asm("mov.b64 %0, {%1,%1};" : "=l"(r) : "r"(__float_as_uint(v)));
    return r;
}
__device__ __forceinline__ float lo32(unsigned long long v) {
    return __uint_as_float((unsigned)v);
}
__device__ __forceinline__ float hi32(unsigned long long v) {
    return __uint_as_float((unsigned)(v >> 32));
}
__device__ __forceinline__ float2 h2f(unsigned u) {
    return __half22float2(*reinterpret_cast<__half2*>(&u));
}

// ---------------- kernels ----------------
// zero degree counters; block 0 also precomputes collapsed edge-attention vecs
__global__ __launch_bounds__(256) void k_init(const float* __restrict__ We1,
                                              const float* __restrict__ ae1,
                                              const float* __restrict__ We2,
                                              const float* __restrict__ ae2) {
    int i = blockIdx.x * blockDim.x + threadIdx.x;
    if (i < NN) g_deg[i] = 0u;
    if (blockIdx.x == 0) {
        int t = threadIdx.x;
        if (t < EDIM * HEADS) {
            int d = t >> 2, h = t & 3;
            float s = 0.f;
            for (int c = 0; c < HID; c++) s += We1[d * C1 + h * HID + c] * ae1[h * HID + c];
            g_v1[t] = s;
        }
        if (t < EDIM) {
            float s = 0.f;
            for (int c = 0; c < HID; c++) s += We2[t * HID + c] * ae2[c];
            g_v2[t] = s;
        }
    }
}

__global__ __launch_bounds__(256) void k_hist(const int* __restrict__ ei) {
    int e = blockIdx.x * blockDim.x + threadIdx.x;
    if (e < NE) atomicAdd(&g_deg[ei[NE + e]], 1u);
}

// single-block exclusive scan of degrees -> g_ptr, g_cnt
__global__ __launch_bounds__(1024) void k_scan() {
    __shared__ unsigned wsum[32];
    const int T = 1024;
    int t = threadIdx.x;
    int per = (NN + T - 1) / T;                 // 49
    int b = t * per, e = min(b + per, NN);
    unsigned s = 0;
    for (int i = b; i < e; i++) s += g_deg[i];
    unsigned lane = t & 31, wid = t >> 5;
    unsigned incl = s;
#pragma unroll
    for (int o = 1; o < 32; o <<= 1) {
        unsigned u = __shfl_up_sync(0xFFFFFFFFu, incl, o);
        if (lane >= (unsigned)o) incl += u;
    }
    if (lane == 31) wsum[wid] = incl;
    __syncthreads();
    if (wid == 0) {
        unsigned v = wsum[lane];
        unsigned vi = v;
#pragma unroll
        for (int o = 1; o < 32; o <<= 1) {
            unsigned u = __shfl_up_sync(0xFFFFFFFFu, vi, o);
            if (lane >= (unsigned)o) vi += u;
        }
        wsum[lane] = vi - v;
    }
    __syncthreads();
    unsigned run = incl - s + wsum[wid];
    for (int i = b; i < e; i++) {
        unsigned d = g_deg[i];
        g_ptr[i] = run;
        g_cnt[i] = run;
        run += d;
    }
    if (t == T - 1) g_ptr[NN] = NE;
}

__global__ __launch_bounds__(256) void k_scatter(const int* __restrict__ ei) {
    int e = blockIdx.x * blockDim.x + threadIdx.x;
    if (e >= NE) return;
    int s = ei[e], d = ei[NE + e];
    unsigned pos = atomicAdd(&g_cnt[d], 1u);
    g_csr[pos] = make_int2(e, s);
}

// ---- h1 = x @ W1 : 16 nodes/block, packed f32x2 over node pairs, fp16 out ----
__global__ __launch_bounds__(256) void k_gemm1(const float* __restrict__ x,
                                               const float* __restrict__ W1) {
    __shared__ float2 xs[IND][8];               // [k][node_pair]
    int node0 = blockIdx.x * 16;
    int t = threadIdx.x;
#pragma unroll
    for (int i = 0; i < 8; i++) {
        int j = i * 256 + t;                    // 0..2047
        int n = j >> 7, k = j & 127;
        float v = x[(size_t)(node0 + n) * IND + k];
        ((float*)&xs[k][n >> 1])[n & 1] = v;
    }
    __syncthreads();
    unsigned long long acc[8];
#pragma unroll
    for (int i = 0; i < 8; i++) acc[i] = 0ull;
#pragma unroll 4
    for (int k = 0; k < IND; k++) {
        unsigned long long w2 = pack2(W1[k * C1 + t]);
#pragma unroll
        for (int i = 0; i < 8; i++) {
            unsigned long long xv = *reinterpret_cast<const unsigned long long*>(&xs[k][i]);
            fma2(acc[i], xv, w2);
        }
    }
    __half* h1 = (__half*)g_h1h;
#pragma unroll
    for (int i = 0; i < 8; i++) {
        h1[(size_t)(node0 + 2 * i) * C1 + t]     = __float2half_rn(lo32(acc[i]));
        h1[(size_t)(node0 + 2 * i + 1) * C1 + t] = __float2half_rn(hi32(acc[i]));
    }
}

// per-node attention dots from fp16 h1 (warp per node; lane owns 8 channels)
__global__ __launch_bounds__(256) void k_att1(const float* __restrict__ as1,
                                              const float* __restrict__ ad1) {
    int n = (blockIdx.x * blockDim.x + threadIdx.x) >> 5;
    int lane = threadIdx.x & 31;
    if (n >= NN) return;
    uint4 hv = g_h1h[(size_t)n * 32 + lane];
    float4 a0 = ((const float4*)as1)[2 * lane], a1 = ((const float4*)as1)[2 * lane + 1];
    float4 d0 = ((const float4*)ad1)[2 * lane], d1 = ((const float4*)ad1)[2 * lane + 1];
    float2 f0 = h2f(hv.x), f1 = h2f(hv.y), f2 = h2f(hv.z), f3 = h2f(hv.w);
    float s = f0.x * a0.x + f0.y * a0.y + f1.x * a0.z + f1.y * a0.w
            + f2.x * a1.x + f2.y * a1.y + f3.x * a1.z + f3.y * a1.w;
    float d = f0.x * d0.x + f0.y * d0.y + f1.x * d0.z + f1.y * d0.w
            + f2.x * d1.x + f2.y * d1.y + f3.x * d1.z + f3.y * d1.w;
#pragma unroll
    for (int o = 4; o >= 1; o >>= 1) {
        s += __shfl_xor_sync(0xFFFFFFFFu, s, o);
        d += __shfl_xor_sync(0xFFFFFFFFu, d, o);
    }
    if ((lane & 7) == 0) {
        int h = lane >> 3;
        ((float*)g_asrc1)[n * 4 + h] = s;
        ((float*)g_adst1)[n * 4 + h] = d;
    }
}

// per-edge: layer-1 exp(logits), layer-2 edge-attr term
__global__ __launch_bounds__(256) void k_edge1(const int* __restrict__ ei,
                                               const float* __restrict__ eattr) {
    __shared__ float v1s[EDIM * HEADS];
    __shared__ float v2s[EDIM];
    if (threadIdx.x < EDIM * HEADS) v1s[threadIdx.x] = g_v1[threadIdx.x];
    if (threadIdx.x < EDIM)         v2s[threadIdx.x] = g_v2[threadIdx.x];
    __syncthreads();
    int e = blockIdx.x * blockDim.x + threadIdx.x;
    if (e >= NE) return;
    int s = ei[e], d = ei[NE + e];
    const float4* ea = (const float4*)(eattr + (size_t)e * EDIM);
    float ae[4] = {0.f, 0.f, 0.f, 0.f};
    float aev2 = 0.f;
#pragma unroll
    for (int j = 0; j < 4; j++) {
        float4 v = ea[j];
        float vals[4] = {v.x, v.y, v.z, v.w};
#pragma unroll
        for (int m = 0; m < 4; m++) {
            int dd = j * 4 + m;
            float ev = vals[m];
#pragma unroll
            for (int h = 0; h < 4; h++) ae[h] = fmaf(ev, v1s[dd * 4 + h], ae[h]);
            aev2 = fmaf(ev, v2s[dd], aev2);
        }
    }
    g_ae2[e] = aev2;
    float4 av = g_asrc1[s], dv = g_adst1[d];
    float4 ex;
    ex.x = __expf(lrelu(av.x + dv.x + ae[0]));
    ex.y = __expf(lrelu(av.y + dv.y + ae[1]));
    ex.z = __expf(lrelu(av.z + dv.z + ae[2]));
    ex.w = __expf(lrelu(av.w + dv.w + ae[3]));
    g_scr1[e] = ex;
}

// layer-1 aggregation: warp per dst node, single fused pass
__global__ __launch_bounds__(256) void k_agg1() {
    int w = (blockIdx.x * blockDim.x + threadIdx.x) >> 5;
    int lane = threadIdx.x & 31;
    if (w >= NN) return;
    unsigned beg = g_ptr[w], end = g_ptr[w + 1];
    int h = lane >> 3;                           // head for this lane's 8 channels
    const float* scr = (const float*)g_scr1;
    float a[8] = {0.f, 0.f, 0.f, 0.f, 0.f, 0.f, 0.f, 0.f};
    float ds = 0.f;
    unsigned j = beg;
    for (; j + 2 <= end; j += 2) {
        int2 e0 = g_csr[j], e1 = g_csr[j + 1];
        float x0 = scr[(size_t)e0.x * 4 + h];
        float x1 = scr[(size_t)e1.x * 4 + h];
        uint4 v0 = g_h1h[(size_t)e0.y * 32 + lane];
        uint4 v1 = g_h1h[(size_t)e1.y * 32 + lane];
        ds += x0 + x1;
        float2 f;
        f = h2f(v0.x); a[0] = fmaf(f.x, x0, a[0]); a[1] = fmaf(f.y, x0, a[1]);
        f = h2f(v0.y); a[2] = fmaf(f.x, x0, a[2]); a[3] = fmaf(f.y, x0, a[3]);
        f = h2f(v0.z); a[4] = fmaf(f.x, x0, a[4]); a[5] = fmaf(f.y, x0, a[5]);
        f = h2f(v0.w); a[6] = fmaf(f.x, x0, a[6]); a[7] = fmaf(f.y, x0, a[7]);
        f = h2f(v1.x); a[0] = fmaf(f.x, x1, a[0]); a[1] = fmaf(f.y, x1, a[1]);
        f = h2f(v1.y); a[2] = fmaf(f.x, x1, a[2]); a[3] = fmaf(f.y, x1, a[3]);
        f = h2f(v1.z); a[4] = fmaf(f.x, x1, a[4]); a[5] = fmaf(f.y, x1, a[5]);
        f = h2f(v1.w); a[6] = fmaf(f.x, x1, a[6]); a[7] = fmaf(f.y, x1, a[7]);
    }
    if (j < end) {
        int2 e0 = g_csr[j];
        float x0 = scr[(size_t)e0.x * 4 + h];
        uint4 v0 = g_h1h[(size_t)e0.y * 32 + lane];
        ds += x0;
        float2 f;
        f = h2f(v0.x); a[0] = fmaf(f.x, x0, a[0]); a[1] = fmaf(f.y, x0, a[1]);
        f = h2f(v0.y); a[2] = fmaf(f.x, x0, a[2]); a[3] = fmaf(f.y, x0, a[3]);
        f = h2f(v0.z); a[4] = fmaf(f.x, x0, a[4]); a[5] = fmaf(f.y, x0, a[5]);
        f = h2f(v0.w); a[6] = fmaf(f.x, x0, a[6]); a[7] = fmaf(f.y, x0, a[7]);
    }
    float inv = 1.f / (ds + 1e-16f);
    float4* od = g_out1 + (size_t)w * 64;
    od[2 * lane]     = make_float4(a[0] * inv, a[1] * inv, a[2] * inv, a[3] * inv);
    od[2 * lane + 1] = make_float4(a[4] * inv, a[5] * inv, a[6] * inv, a[7] * inv);
}

// h2 = relu(out1+b1) @ W2 + layer-2 attention dots. 8 nodes/block, f32x2.
__global__ __launch_bounds__(256) void k_gemm2(const float* __restrict__ W2,
                                               const float* __restrict__ b1,
                                               const float* __restrict__ as2,
                                               const float* __restrict__ ad2) {
    __shared__ float xs[8][C1];                 // 8 KB
    int node0 = blockIdx.x * 8;
    int t = threadIdx.x;
#pragma unroll
    for (int i = 0; i < 2; i++) {
        int j = i * 256 + t;                    // float4 index, 0..511
        int n = j >> 6, q = j & 63;
        float4 v = g_out1[(size_t)(node0 + n) * 64 + q];
        float4 b = ((const float4*)b1)[q];
        v.x = fmaxf(v.x + b.x, 0.f); v.y = fmaxf(v.y + b.y, 0.f);
        v.z = fmaxf(v.z + b.z, 0.f); v.w = fmaxf(v.w + b.w, 0.f);
        ((float4*)&xs[n][0])[q] = v;
    }
    __syncthreads();
    int ni = t >> 5, c = t & 31;                // node-in-block, col pair
    unsigned long long acc = 0ull;
#pragma unroll 4
    for (int k = 0; k < C1; k++) {
        unsigned long long xv = pack2(xs[ni][k]);
        unsigned long long wv = *reinterpret_cast<const unsigned long long*>(&W2[k * HID + 2 * c]);
        fma2(acc, xv, wv);
    }
    float vlo = lo32(acc), vhi = hi32(acc);
    g_h2h[(size_t)(node0 + ni) * 32 + c] = __floats2half2_rn(vlo, vhi);
    float rs = vlo * as2[2 * c] + vhi * as2[2 * c + 1];
    float rd = vlo * ad2[2 * c] + vhi * ad2[2 * c + 1];
#pragma unroll
    for (int o = 16; o >= 1; o >>= 1) {
        rs += __shfl_xor_sync(0xFFFFFFFFu, rs, o);
        rd += __shfl_xor_sync(0xFFFFFFFFu, rd, o);
    }
    if (c == 0) {
        g_asrc2[node0 + ni] = rs;
        g_adst2[node0 + ni] = rd;
    }
}

// layer-2 aggregation fused with final linear: warp per dst node
__global__ __launch_bounds__(256) void k_agg2(const float* __restrict__ b2,
                                              const float* __restrict__ Wlin,
                                              const float* __restrict__ blin,
                                              float* __restrict__ out) {
    int w = (blockIdx.x * blockDim.x + threadIdx.x) >> 5;
    int lane = threadIdx.x & 31;
    if (w >= NN) return;
    unsigned beg = g_ptr[w], end = g_ptr[w + 1];
    float adw = g_adst2[w];
    float2 acc = make_float2(0.f, 0.f);
    float ds = 0.f;
    unsigned j = beg;
    for (; j + 2 <= end; j += 2) {
        int2 e0 = g_csr[j], e1 = g_csr[j + 1];
        float s0 = g_asrc2[e0.y], s1 = g_asrc2[e1.y];
        float t0 = g_ae2[e0.x],  t1 = g_ae2[e1.x];
        __half2 v0 = g_h2h[(size_t)e0.y * 32 + lane];
        __half2 v1 = g_h2h[(size_t)e1.y * 32 + lane];
        float al0 = __expf(lrelu(s0 + adw + t0));
        float al1 = __expf(lrelu(s1 + adw + t1));
        ds += al0 + al1;
        float2 f0 = __half22float2(v0), f1 = __half22float2(v1);
        acc.x = fmaf(f0.x, al0, acc.x); acc.y = fmaf(f0.y, al0, acc.y);
        acc.x = fmaf(f1.x, al1, acc.x); acc.y = fmaf(f1.y, al1, acc.y);
    }
    if (j < end) {
        int2 e0 = g_csr[j];
        float al0 = __expf(lrelu(g_asrc2[e0.y] + adw + g_ae2[e0.x]));
        ds += al0;
        float2 f0 = __half22float2(g_h2h[(size_t)e0.y * 32 + lane]);
        acc.x = fmaf(f0.x, al0, acc.x); acc.y = fmaf(f0.y, al0, acc.y);
    }
    float inv = 1.f / (ds + 1e-16f);
    float v0 = fmaxf(acc.x * inv + b2[2 * lane], 0.f);
    float v1 = fmaxf(acc.y * inv + b2[2 * lane + 1], 0.f);
    float r = v0 * Wlin[2 * lane] + v1 * Wlin[2 * lane + 1];
#pragma unroll
    for (int o = 16; o >= 1; o >>= 1) r += __shfl_xor_sync(0xFFFFFFFFu, r, o);
    if (lane == 0) out[w] = r + blin[0];
}

// ---------------- launch ----------------
extern "C" void kernel_launch(void* const* d_in, const int* in_sizes, int n_in,
                              void* d_out, int out_size) {
    const float* x     = (const float*)d_in[0];
    const int*   ei    = (const int*)d_in[1];
    const float* eattr = (const float*)d_in[2];
    const float* W1    = (const float*)d_in[3];
    const float* We1   = (const float*)d_in[4];
    const float* as1   = (const float*)d_in[5];
    const float* ad1   = (const float*)d_in[6];
    const float* ae1   = (const float*)d_in[7];
    const float* b1    = (const float*)d_in[8];
    const float* W2    = (const float*)d_in[9];
    const float* We2   = (const float*)d_in[10];
    const float* as2   = (const float*)d_in[11];
    const float* ad2   = (const float*)d_in[12];
    const float* ae2   = (const float*)d_in[13];
    const float* b2    = (const float*)d_in[14];
    const float* Wlin  = (const float*)d_in[15];
    const float* blin  = (const float*)d_in[16];
    float* out = (float*)d_out;

    k_init<<<(NN + 255) / 256, 256>>>(We1, ae1, We2, ae2);
    k_hist<<<NE / 256, 256>>>(ei);
    k_scan<<<1, 1024>>>();
    k_scatter<<<NE / 256, 256>>>(ei);
    k_gemm1<<<NN / 16, 256>>>(x, W1);
    k_att1<<<(NN * 32 + 255) / 256, 256>>>(as1, ad1);
    k_edge1<<<NE / 256, 256>>>(ei, eattr);
    k_agg1<<<(NN * 32 + 255) / 256, 256>>>();
    k_gemm2<<<NN / 8, 256>>>(W2, b1, as2, ad2);
    k_agg2<<<(NN * 32 + 255) / 256, 256>>>(b2, Wlin, blin, out);
}

// round 5
// speedup vs baseline: 1.0894x; 1.0894x over previous
#include <cuda_runtime.h>
#include <cuda_fp16.h>

#define NN 50000
#define NE 800000
#define IND 128
#define HID 64
#define HEADS 4
#define C1 256            // HEADS*HID
#define EDIM 16

// ---------------- scratch (device globals) ----------------
__device__ uint4    g_h1h[NN * 32];         // [N,256] h1, fp16
__device__ __half2  g_out1h[NN * 128];      // [N,256] relu(agg1+b1), fp16
__device__ __half2  g_h2h[NN * 32];         // [N,64]  h2, fp16
__device__ float4   g_scr1[NE];             // exp(logits) 4 heads, AT CSR POS
__device__ float    g_ae2[NE];              // layer-2 edge term, AT CSR POS
__device__ int      g_csrc[NE];             // src node, AT CSR POS
__device__ float4   g_asrc1[NN], g_adst1[NN];
__device__ float    g_asrc2[NN], g_adst2[NN];
__device__ float    g_v1[EDIM * HEADS];
__device__ float    g_v2[EDIM];
__device__ unsigned g_deg[NN];
__device__ unsigned g_cnt[NN];
__device__ unsigned g_ptr[NN + 1];

// ---------------- helpers ----------------
__device__ __forceinline__ float lrelu(float x) { return x > 0.f ? x : 0.2f * x; }

__device__ __forceinline__ void fma2(unsigned long long& d,
                                     unsigned long long a, unsigned long long b) {
    asm("fma.rn.f32x2 %0, %1, %2, %0;" : "+l"(d) : "l"(a), "l"(b));
}
__device__ __forceinline__ unsigned long long pack2(float v) {
    unsigned long long r;
    asm("mov.b64 %0, {%1,%1};" : "=l"(r) : "r"(__float_as_uint(v)));
    return r;
}
__device__ __forceinline__ float lo32(unsigned long long v) {
    return __uint_as_float((unsigned)v);
}
__device__ __forceinline__ float hi32(unsigned long long v) {
    return __uint_as_float((unsigned)(v >> 32));
}
__device__ __forceinline__ float2 h2f(unsigned u) {
    return __half22float2(*reinterpret_cast<__half2*>(&u));
}

// ---------------- kernels ----------------
__global__ __launch_bounds__(256) void k_init(const float* __restrict__ We1,
                                              const float* __restrict__ ae1,
                                              const float* __restrict__ We2,
                                              const float* __restrict__ ae2) {
    int i = blockIdx.x * blockDim.x + threadIdx.x;
    if (i < NN) g_deg[i] = 0u;
    if (blockIdx.x == 0) {
        int t = threadIdx.x;
        if (t < EDIM * HEADS) {
            int d = t >> 2, h = t & 3;
            float s = 0.f;
            for (int c = 0; c < HID; c++) s += We1[d * C1 + h * HID + c] * ae1[h * HID + c];
            g_v1[t] = s;
        }
        if (t < EDIM) {
            float s = 0.f;
            for (int c = 0; c < HID; c++) s += We2[t * HID + c] * ae2[c];
            g_v2[t] = s;
        }
    }
}

__global__ __launch_bounds__(256) void k_hist(const int* __restrict__ ei) {
    int e = blockIdx.x * blockDim.x + threadIdx.x;
    if (e < NE) atomicAdd(&g_deg[ei[NE + e]], 1u);
}

// single-block exclusive scan of degrees -> g_ptr, g_cnt
__global__ __launch_bounds__(1024) void k_scan() {
    __shared__ unsigned wsum[32];
    const int T = 1024;
    int t = threadIdx.x;
    int per = (NN + T - 1) / T;
    int b = t * per, e = min(b + per, NN);
    unsigned s = 0;
    for (int i = b; i < e; i++) s += g_deg[i];
    unsigned lane = t & 31, wid = t >> 5;
    unsigned incl = s;
#pragma unroll
    for (int o = 1; o < 32; o <<= 1) {
        unsigned u = __shfl_up_sync(0xFFFFFFFFu, incl, o);
        if (lane >= (unsigned)o) incl += u;
    }
    if (lane == 31) wsum[wid] = incl;
    __syncthreads();
    if (wid == 0) {
        unsigned v = wsum[lane];
        unsigned vi = v;
#pragma unroll
        for (int o = 1; o < 32; o <<= 1) {
            unsigned u = __shfl_up_sync(0xFFFFFFFFu, vi, o);
            if (lane >= (unsigned)o) vi += u;
        }
        wsum[lane] = vi - v;
    }
    __syncthreads();
    unsigned run = incl - s + wsum[wid];
    for (int i = b; i < e; i++) {
        unsigned d = g_deg[i];
        g_ptr[i] = run;
        g_cnt[i] = run;
        run += d;
    }
    if (t == T - 1) g_ptr[NN] = NE;
}

// ---- h1 = x @ W1 : 32 nodes/block, packed f32x2, fp16 output ----
__global__ __launch_bounds__(256) void k_gemm1(const float* __restrict__ x,
                                               const float* __restrict__ W1) {
    __shared__ float2 xs[IND][17];              // [k][node_pair], padded
    int node0 = blockIdx.x * 32;
    int t = threadIdx.x;
#pragma unroll
    for (int i = 0; i < 16; i++) {
        int j = i * 256 + t;                    // 0..4095
        int n = j >> 7, k = j & 127;
        float v = (node0 + n < NN) ? x[(size_t)(node0 + n) * IND + k] : 0.f;
        ((float*)&xs[k][n >> 1])[n & 1] = v;
    }
    __syncthreads();
    unsigned long long acc[16];
#pragma unroll
    for (int i = 0; i < 16; i++) acc[i] = 0ull;
#pragma unroll 2
    for (int k = 0; k < IND; k++) {
        unsigned long long w2 = pack2(W1[k * C1 + t]);
#pragma unroll
        for (int i = 0; i < 16; i++) {
            unsigned long long xv = *reinterpret_cast<const unsigned long long*>(&xs[k][i]);
            fma2(acc[i], xv, w2);
        }
    }
    __half* h1 = (__half*)g_h1h;
#pragma unroll
    for (int i = 0; i < 16; i++) {
        int n0 = node0 + 2 * i;
        if (n0 < NN)     h1[(size_t)n0 * C1 + t]       = __float2half_rn(lo32(acc[i]));
        if (n0 + 1 < NN) h1[(size_t)(n0 + 1) * C1 + t] = __float2half_rn(hi32(acc[i]));
    }
}

// per-node attention dots from fp16 h1 (warp per node)
__global__ __launch_bounds__(256) void k_att1(const float* __restrict__ as1,
                                              const float* __restrict__ ad1) {
    int n = (blockIdx.x * blockDim.x + threadIdx.x) >> 5;
    int lane = threadIdx.x & 31;
    if (n >= NN) return;
    uint4 hv = g_h1h[(size_t)n * 32 + lane];
    float4 a0 = ((const float4*)as1)[2 * lane], a1 = ((const float4*)as1)[2 * lane + 1];
    float4 d0 = ((const float4*)ad1)[2 * lane], d1 = ((const float4*)ad1)[2 * lane + 1];
    float2 f0 = h2f(hv.x), f1 = h2f(hv.y), f2 = h2f(hv.z), f3 = h2f(hv.w);
    float s = f0.x * a0.x + f0.y * a0.y + f1.x * a0.z + f1.y * a0.w
            + f2.x * a1.x + f2.y * a1.y + f3.x * a1.z + f3.y * a1.w;
    float d = f0.x * d0.x + f0.y * d0.y + f1.x * d0.z + f1.y * d0.w
            + f2.x * d1.x + f2.y * d1.y + f3.x * d1.z + f3.y * d1.w;
#pragma unroll
    for (int o = 4; o >= 1; o >>= 1) {
        s += __shfl_xor_sync(0xFFFFFFFFu, s, o);
        d += __shfl_xor_sync(0xFFFFFFFFu, d, o);
    }
    if ((lane & 7) == 0) {
        int h = lane >> 3;
        ((float*)g_asrc1)[n * 4 + h] = s;
        ((float*)g_adst1)[n * 4 + h] = d;
    }
}

// per-edge logits + CSR scatter fused: write exp/ae2/src AT the CSR slot
__global__ __launch_bounds__(256) void k_edge1(const int* __restrict__ ei,
                                               const float* __restrict__ eattr) {
    __shared__ float v1s[EDIM * HEADS];
    __shared__ float v2s[EDIM];
    if (threadIdx.x < EDIM * HEADS) v1s[threadIdx.x] = g_v1[threadIdx.x];
    if (threadIdx.x < EDIM)         v2s[threadIdx.x] = g_v2[threadIdx.x];
    __syncthreads();
    int e = blockIdx.x * blockDim.x + threadIdx.x;
    if (e >= NE) return;
    int s = ei[e], d = ei[NE + e];
    const float4* ea = (const float4*)(eattr + (size_t)e * EDIM);
    float ae[4] = {0.f, 0.f, 0.f, 0.f};
    float aev2 = 0.f;
#pragma unroll
    for (int j = 0; j < 4; j++) {
        float4 v = ea[j];
        float vals[4] = {v.x, v.y, v.z, v.w};
#pragma unroll
        for (int m = 0; m < 4; m++) {
            int dd = j * 4 + m;
            float ev = vals[m];
#pragma unroll
            for (int h = 0; h < 4; h++) ae[h] = fmaf(ev, v1s[dd * 4 + h], ae[h]);
            aev2 = fmaf(ev, v2s[dd], aev2);
        }
    }
    float4 av = g_asrc1[s], dv = g_adst1[d];
    float4 ex;
    ex.x = __expf(lrelu(av.x + dv.x + ae[0]));
    ex.y = __expf(lrelu(av.y + dv.y + ae[1]));
    ex.z = __expf(lrelu(av.z + dv.z + ae[2]));
    ex.w = __expf(lrelu(av.w + dv.w + ae[3]));
    unsigned pos = atomicAdd(&g_cnt[d], 1u);
    g_csrc[pos] = s;
    g_scr1[pos] = ex;
    g_ae2[pos] = aev2;
}

// layer-1 aggregation: warp per dst node; sequential scr reads, random h1 gather
// epilogue applies bias + relu and stores fp16
__global__ __launch_bounds__(256) void k_agg1(const float* __restrict__ b1) {
    int w = (blockIdx.x * blockDim.x + threadIdx.x) >> 5;
    int lane = threadIdx.x & 31;
    if (w >= NN) return;
    unsigned beg = g_ptr[w], end = g_ptr[w + 1];
    int h = lane >> 3;
    const float* scr = (const float*)g_scr1;
    float a[8] = {0.f, 0.f, 0.f, 0.f, 0.f, 0.f, 0.f, 0.f};
    float ds = 0.f;
    unsigned j = beg;
    for (; j + 2 <= end; j += 2) {
        int s0 = g_csrc[j], s1 = g_csrc[j + 1];
        float x0 = scr[(size_t)j * 4 + h];
        float x1 = scr[(size_t)(j + 1) * 4 + h];
        uint4 v0 = g_h1h[(size_t)s0 * 32 + lane];
        uint4 v1 = g_h1h[(size_t)s1 * 32 + lane];
        ds += x0 + x1;
        float2 f;
        f = h2f(v0.x); a[0] = fmaf(f.x, x0, a[0]); a[1] = fmaf(f.y, x0, a[1]);
        f = h2f(v0.y); a[2] = fmaf(f.x, x0, a[2]); a[3] = fmaf(f.y, x0, a[3]);
        f = h2f(v0.z); a[4] = fmaf(f.x, x0, a[4]); a[5] = fmaf(f.y, x0, a[5]);
        f = h2f(v0.w); a[6] = fmaf(f.x, x0, a[6]); a[7] = fmaf(f.y, x0, a[7]);
        f = h2f(v1.x); a[0] = fmaf(f.x, x1, a[0]); a[1] = fmaf(f.y, x1, a[1]);
        f = h2f(v1.y); a[2] = fmaf(f.x, x1, a[2]); a[3] = fmaf(f.y, x1, a[3]);
        f = h2f(v1.z); a[4] = fmaf(f.x, x1, a[4]); a[5] = fmaf(f.y, x1, a[5]);
        f = h2f(v1.w); a[6] = fmaf(f.x, x1, a[6]); a[7] = fmaf(f.y, x1, a[7]);
    }
    if (j < end) {
        int s0 = g_csrc[j];
        float x0 = scr[(size_t)j * 4 + h];
        uint4 v0 = g_h1h[(size_t)s0 * 32 + lane];
        ds += x0;
        float2 f;
        f = h2f(v0.x); a[0] = fmaf(f.x, x0, a[0]); a[1] = fmaf(f.y, x0, a[1]);
        f = h2f(v0.y); a[2] = fmaf(f.x, x0, a[2]); a[3] = fmaf(f.y, x0, a[3]);
        f = h2f(v0.z); a[4] = fmaf(f.x, x0, a[4]); a[5] = fmaf(f.y, x0, a[5]);
        f = h2f(v0.w); a[6] = fmaf(f.x, x0, a[6]); a[7] = fmaf(f.y, x0, a[7]);
    }
    float inv = 1.f / (ds + 1e-16f);
    float4 b0 = ((const float4*)b1)[2 * lane];
    float4 b1v = ((const float4*)b1)[2 * lane + 1];
    __half2 r0 = __floats2half2_rn(fmaxf(a[0] * inv + b0.x, 0.f),
                                   fmaxf(a[1] * inv + b0.y, 0.f));
    __half2 r1 = __floats2half2_rn(fmaxf(a[2] * inv + b0.z, 0.f),
                                   fmaxf(a[3] * inv + b0.w, 0.f));
    __half2 r2 = __floats2half2_rn(fmaxf(a[4] * inv + b1v.x, 0.f),
                                   fmaxf(a[5] * inv + b1v.y, 0.f));
    __half2 r3 = __floats2half2_rn(fmaxf(a[6] * inv + b1v.z, 0.f),
                                   fmaxf(a[7] * inv + b1v.w, 0.f));
    uint4 pk;
    pk.x = *(unsigned*)&r0; pk.y = *(unsigned*)&r1;
    pk.z = *(unsigned*)&r2; pk.w = *(unsigned*)&r3;
    *reinterpret_cast<uint4*>(&g_out1h[(size_t)w * 128 + lane * 4]) = pk;
}

// h2 = out1 @ W2 (+ layer-2 dots). 16 nodes/block, dup-packed x in smem.
__global__ __launch_bounds__(256) void k_gemm2(const float* __restrict__ W2,
                                               const float* __restrict__ as2,
                                               const float* __restrict__ ad2) {
    __shared__ float2 xsp[16][C1];              // 32 KB, (x,x) duplicated pairs
    int node0 = blockIdx.x * 16;
    int t = threadIdx.x;
#pragma unroll
    for (int i = 0; i < 8; i++) {
        int j = i * 256 + t;                    // 0..2047 (half2 units)
        int n = j >> 7, q = j & 127;
        float2 f = __half22float2(g_out1h[(size_t)(node0 + n) * 128 + q]);
        xsp[n][2 * q]     = make_float2(f.x, f.x);
        xsp[n][2 * q + 1] = make_float2(f.y, f.y);
    }
    __syncthreads();
    int c = t & 31, ng = t >> 5;                // col-pair, node-group
    int nA = 2 * ng, nB = 2 * ng + 1;
    unsigned long long accA = 0ull, accB = 0ull;
#pragma unroll 4
    for (int k = 0; k < C1; k++) {
        unsigned long long wv = *reinterpret_cast<const unsigned long long*>(&W2[k * HID + 2 * c]);
        fma2(accA, *reinterpret_cast<const unsigned long long*>(&xsp[nA][k]), wv);
        fma2(accB, *reinterpret_cast<const unsigned long long*>(&xsp[nB][k]), wv);
    }
    float loA = lo32(accA), hiA = hi32(accA);
    float loB = lo32(accB), hiB = hi32(accB);
    g_h2h[(size_t)(node0 + nA) * 32 + c] = __floats2half2_rn(loA, hiA);
    g_h2h[(size_t)(node0 + nB) * 32 + c] = __floats2half2_rn(loB, hiB);
    float sA = loA * as2[2 * c] + hiA * as2[2 * c + 1];
    float dA = loA * ad2[2 * c] + hiA * ad2[2 * c + 1];
    float sB = loB * as2[2 * c] + hiB * as2[2 * c + 1];
    float dB = loB * ad2[2 * c] + hiB * ad2[2 * c + 1];
#pragma unroll
    for (int o = 16; o >= 1; o >>= 1) {
        sA += __shfl_xor_sync(0xFFFFFFFFu, sA, o);
        dA += __shfl_xor_sync(0xFFFFFFFFu, dA, o);
        sB += __shfl_xor_sync(0xFFFFFFFFu, sB, o);
        dB += __shfl_xor_sync(0xFFFFFFFFu, dB, o);
    }
    if (c == 0) {
        g_asrc2[node0 + nA] = sA;
        g_adst2[node0 + nA] = dA;
        g_asrc2[node0 + nB] = sB;
        g_adst2[node0 + nB] = dB;
    }
}

// layer-2 aggregation + final linear: warp per dst node
__global__ __launch_bounds__(256) void k_agg2(const float* __restrict__ b2,
                                              const float* __restrict__ Wlin,
                                              const float* __restrict__ blin,
                                              float* __restrict__ out) {
    int w = (blockIdx.x * blockDim.x + threadIdx.x) >> 5;
    int lane = threadIdx.x & 31;
    if (w >= NN) return;
    unsigned beg = g_ptr[w], end = g_ptr[w + 1];
    float adw = g_adst2[w];
    float2 acc = make_float2(0.f, 0.f);
    float ds = 0.f;
    unsigned j = beg;
    for (; j + 2 <= end; j += 2) {
        int s0 = g_csrc[j], s1 = g_csrc[j + 1];
        float t0 = g_ae2[j], t1 = g_ae2[j + 1];
        float a0 = g_asrc2[s0], a1 = g_asrc2[s1];
        __half2 v0 = g_h2h[(size_t)s0 * 32 + lane];
        __half2 v1 = g_h2h[(size_t)s1 * 32 + lane];
        float al0 = __expf(lrelu(a0 + adw + t0));
        float al1 = __expf(lrelu(a1 + adw + t1));
        ds += al0 + al1;
        float2 f0 = __half22float2(v0), f1 = __half22float2(v1);
        acc.x = fmaf(f0.x, al0, acc.x); acc.y = fmaf(f0.y, al0, acc.y);
        acc.x = fmaf(f1.x, al1, acc.x); acc.y = fmaf(f1.y, al1, acc.y);
    }
    if (j < end) {
        int s0 = g_csrc[j];
        float al0 = __expf(lrelu(g_asrc2[s0] + adw + g_ae2[j]));
        ds += al0;
        float2 f0 = __half22float2(g_h2h[(size_t)s0 * 32 + lane]);
        acc.x = fmaf(f0.x, al0, acc.x); acc.y = fmaf(f0.y, al0, acc.y);
    }
    float inv = 1.f / (ds + 1e-16f);
    float v0 = fmaxf(acc.x * inv + b2[2 * lane], 0.f);
    float v1 = fmaxf(acc.y * inv + b2[2 * lane + 1], 0.f);
    float r = v0 * Wlin[2 * lane] + v1 * Wlin[2 * lane + 1];
#pragma unroll
    for (int o = 16; o >= 1; o >>= 1) r += __shfl_xor_sync(0xFFFFFFFFu, r, o);
    if (lane == 0) out[w] = r + blin[0];
}

// ---------------- launch ----------------
extern "C" void kernel_launch(void* const* d_in, const int* in_sizes, int n_in,
                              void* d_out, int out_size) {
    const float* x     = (const float*)d_in[0];
    const int*   ei    = (const int*)d_in[1];
    const float* eattr = (const float*)d_in[2];
    const float* W1    = (const float*)d_in[3];
    const float* We1   = (const float*)d_in[4];
    const float* as1   = (const float*)d_in[5];
    const float* ad1   = (const float*)d_in[6];
    const float* ae1   = (const float*)d_in[7];
    const float* b1    = (const float*)d_in[8];
    const float* W2    = (const float*)d_in[9];
    const float* We2   = (const float*)d_in[10];
    const float* as2   = (const float*)d_in[11];
    const float* ad2   = (const float*)d_in[12];
    const float* ae2   = (const float*)d_in[13];
    const float* b2    = (const float*)d_in[14];
    const float* Wlin  = (const float*)d_in[15];
    const float* blin  = (const float*)d_in[16];
    float* out = (float*)d_out;

    k_init<<<(NN + 255) / 256, 256>>>(We1, ae1, We2, ae2);
    k_hist<<<NE / 256, 256>>>(ei);
    k_scan<<<1, 1024>>>();
    k_gemm1<<<(NN + 31) / 32, 256>>>(x, W1);
    k_att1<<<(NN * 32 + 255) / 256, 256>>>(as1, ad1);
    k_edge1<<<NE / 256, 256>>>(ei, eattr);
    k_agg1<<<(NN * 32 + 255) / 256, 256>>>(b1);
    k_gemm2<<<NN / 16, 256>>>(W2, as2, ad2);
    k_agg2<<<(NN * 32 + 255) / 256, 256>>>(b2, Wlin, blin, out);
}

// round 6
// speedup vs baseline: 1.4626x; 1.3425x over previous
#include <cuda_runtime.h>
#include <cuda_fp16.h>

#define NN 50000
#define NE 800000
#define IND 128
#define HID 64
#define HEADS 4
#define C1 256            // HEADS*HID
#define EDIM 16

// ---------------- scratch (device globals) ----------------
__device__ uint4    g_h1h[NN * 32];         // [N,256] h1, fp16
__device__ __half2  g_out1h[NN * 128];      // [N,256] relu(agg1+b1), fp16
__device__ __half2  g_h2h[NN * 32];         // [N,64]  h2, fp16
__device__ float4   g_scr1[NE];             // exp(logits) 4 heads, AT CSR POS
__device__ float    g_ae2[NE];              // layer-2 edge term, AT CSR POS
__device__ int      g_csrc[NE];             // src node, AT CSR POS
__device__ float4   g_asrc1[NN], g_adst1[NN];
__device__ float    g_asrc2[NN], g_adst2[NN];
__device__ float    g_v1[EDIM * HEADS];
__device__ float    g_v2[EDIM];
__device__ unsigned g_deg[NN];
__device__ unsigned g_cnt[NN];
__device__ unsigned g_ptr[NN + 1];

// ---------------- helpers ----------------
__device__ __forceinline__ float lrelu(float x) { return x > 0.f ? x : 0.2f * x; }
__device__ __forceinline__ float2 h2f(unsigned u) {
    return __half22float2(*reinterpret_cast<__half2*>(&u));
}
__device__ __forceinline__ void mma16816(float* c, const unsigned* a,
                                         unsigned b0, unsigned b1) {
    asm volatile(
        "mma.sync.aligned.m16n8k16.row.col.f32.f16.f16.f32 "
        "{%0,%1,%2,%3}, {%4,%5,%6,%7}, {%8,%9}, {%0,%1,%2,%3};"
        : "+f"(c[0]), "+f"(c[1]), "+f"(c[2]), "+f"(c[3])
        : "r"(a[0]), "r"(a[1]), "r"(a[2]), "r"(a[3]), "r"(b0), "r"(b1));
}

// ---------------- kernels ----------------
__global__ __launch_bounds__(256) void k_init(const float* __restrict__ We1,
                                              const float* __restrict__ ae1,
                                              const float* __restrict__ We2,
                                              const float* __restrict__ ae2) {
    int i = blockIdx.x * blockDim.x + threadIdx.x;
    if (i < NN) g_deg[i] = 0u;
    if (blockIdx.x == 0) {
        int t = threadIdx.x;
        if (t < EDIM * HEADS) {
            int d = t >> 2, h = t & 3;
            float s = 0.f;
            for (int c = 0; c < HID; c++) s += We1[d * C1 + h * HID + c] * ae1[h * HID + c];
            g_v1[t] = s;
        }
        if (t < EDIM) {
            float s = 0.f;
            for (int c = 0; c < HID; c++) s += We2[t * HID + c] * ae2[c];
            g_v2[t] = s;
        }
    }
}

__global__ __launch_bounds__(256) void k_hist(const int* __restrict__ ei) {
    int e = blockIdx.x * blockDim.x + threadIdx.x;
    if (e < NE) atomicAdd(&g_deg[ei[NE + e]], 1u);
}

// single-block exclusive scan of degrees -> g_ptr, g_cnt
__global__ __launch_bounds__(1024) void k_scan() {
    __shared__ unsigned wsum[32];
    const int T = 1024;
    int t = threadIdx.x;
    int per = (NN + T - 1) / T;
    int b = t * per, e = min(b + per, NN);
    unsigned s = 0;
    for (int i = b; i < e; i++) s += g_deg[i];
    unsigned lane = t & 31, wid = t >> 5;
    unsigned incl = s;
#pragma unroll
    for (int o = 1; o < 32; o <<= 1) {
        unsigned u = __shfl_up_sync(0xFFFFFFFFu, incl, o);
        if (lane >= (unsigned)o) incl += u;
    }
    if (lane == 31) wsum[wid] = incl;
    __syncthreads();
    if (wid == 0) {
        unsigned v = wsum[lane];
        unsigned vi = v;
#pragma unroll
        for (int o = 1; o < 32; o <<= 1) {
            unsigned u = __shfl_up_sync(0xFFFFFFFFu, vi, o);
            if (lane >= (unsigned)o) vi += u;
        }
        wsum[lane] = vi - v;
    }
    __syncthreads();
    unsigned run = incl - s + wsum[wid];
    for (int i = b; i < e; i++) {
        unsigned d = g_deg[i];
        g_ptr[i] = run;
        g_cnt[i] = run;
        run += d;
    }
    if (t == T - 1) g_ptr[NN] = NE;
}

// ---- h1 = x @ W1 via HMMA: block tile 64 nodes x 128 cols ----
#define XS1_STRIDE 136                    // 128 + 8 halfs pad
#define WS1_STRIDE 136
#define G1_SMEM ((64 * XS1_STRIDE + 128 * WS1_STRIDE) * 2)

__global__ __launch_bounds__(256) void k_gemm1(const float* __restrict__ x,
                                               const float* __restrict__ W1) {
    extern __shared__ __half sm1[];
    __half* xs = sm1;                     // [64][136]
    __half* ws = sm1 + 64 * XS1_STRIDE;   // [128 n][136 k] (transposed)
    int t = threadIdx.x;
    int node0 = blockIdx.x * 64;
    int ncol0 = blockIdx.y * 128;
    // load x tile (fp32 -> fp16)
#pragma unroll
    for (int i = 0; i < 8; i++) {
        int j = i * 256 + t;              // float4 idx; 32 per row
        int m = j >> 5, kq = j & 31;
        float4 v = make_float4(0.f, 0.f, 0.f, 0.f);
        if (node0 + m < NN) v = ((const float4*)x)[(size_t)(node0 + m) * 32 + kq];
        *(__half2*)&xs[m * XS1_STRIDE + kq * 4]     = __floats2half2_rn(v.x, v.y);
        *(__half2*)&xs[m * XS1_STRIDE + kq * 4 + 2] = __floats2half2_rn(v.z, v.w);
    }
    // load W1 tile transposed: ws[n][k]
#pragma unroll
    for (int i = 0; i < 16; i++) {
        int j = i * 256 + t;              // 4096 float4
        int k = j >> 5, nq = j & 31;
        float4 v = ((const float4*)(W1 + (size_t)k * C1 + ncol0))[nq];
        int n = nq * 4;
        ws[(n + 0) * WS1_STRIDE + k] = __float2half_rn(v.x);
        ws[(n + 1) * WS1_STRIDE + k] = __float2half_rn(v.y);
        ws[(n + 2) * WS1_STRIDE + k] = __float2half_rn(v.z);
        ws[(n + 3) * WS1_STRIDE + k] = __float2half_rn(v.w);
    }
    __syncthreads();
    int warp = t >> 5, lane = t & 31;
    int wm = warp & 1, wn = warp >> 1;    // 2 x 4 warp grid; warp tile 32x32
    int m_base = wm * 32, n_base = wn * 32;
    int r = lane >> 2, kp = (lane & 3) * 2;
    float c[2][4][4];
#pragma unroll
    for (int i = 0; i < 2; i++)
#pragma unroll
        for (int j = 0; j < 4; j++)
#pragma unroll
            for (int q = 0; q < 4; q++) c[i][j][q] = 0.f;
#pragma unroll
    for (int k0 = 0; k0 < IND; k0 += 16) {
        unsigned a[2][4];
#pragma unroll
        for (int mt = 0; mt < 2; mt++) {
            int row = m_base + mt * 16 + r;
            a[mt][0] = *(unsigned*)&xs[row * XS1_STRIDE + k0 + kp];
            a[mt][1] = *(unsigned*)&xs[(row + 8) * XS1_STRIDE + k0 + kp];
            a[mt][2] = *(unsigned*)&xs[row * XS1_STRIDE + k0 + 8 + kp];
            a[mt][3] = *(unsigned*)&xs[(row + 8) * XS1_STRIDE + k0 + 8 + kp];
        }
#pragma unroll
        for (int nt = 0; nt < 4; nt++) {
            int n = n_base + nt * 8 + r;
            unsigned b0 = *(unsigned*)&ws[n * WS1_STRIDE + k0 + kp];
            unsigned b1 = *(unsigned*)&ws[n * WS1_STRIDE + k0 + 8 + kp];
            mma16816(c[0][nt], a[0], b0, b1);
            mma16816(c[1][nt], a[1], b0, b1);
        }
    }
    __half* h1 = (__half*)g_h1h;
#pragma unroll
    for (int mt = 0; mt < 2; mt++) {
#pragma unroll
        for (int nt = 0; nt < 4; nt++) {
            int row = node0 + m_base + mt * 16 + r;
            int col = ncol0 + n_base + nt * 8 + kp;
            if (row < NN)
                *(__half2*)&h1[(size_t)row * C1 + col] =
                    __floats2half2_rn(c[mt][nt][0], c[mt][nt][1]);
            if (row + 8 < NN)
                *(__half2*)&h1[(size_t)(row + 8) * C1 + col] =
                    __floats2half2_rn(c[mt][nt][2], c[mt][nt][3]);
        }
    }
}

// per-node attention dots from fp16 h1 (warp per node)
__global__ __launch_bounds__(256) void k_att1(const float* __restrict__ as1,
                                              const float* __restrict__ ad1) {
    int n = (blockIdx.x * blockDim.x + threadIdx.x) >> 5;
    int lane = threadIdx.x & 31;
    if (n >= NN) return;
    uint4 hv = g_h1h[(size_t)n * 32 + lane];
    float4 a0 = ((const float4*)as1)[2 * lane], a1 = ((const float4*)as1)[2 * lane + 1];
    float4 d0 = ((const float4*)ad1)[2 * lane], d1 = ((const float4*)ad1)[2 * lane + 1];
    float2 f0 = h2f(hv.x), f1 = h2f(hv.y), f2 = h2f(hv.z), f3 = h2f(hv.w);
    float s = f0.x * a0.x + f0.y * a0.y + f1.x * a0.z + f1.y * a0.w
            + f2.x * a1.x + f2.y * a1.y + f3.x * a1.z + f3.y * a1.w;
    float d = f0.x * d0.x + f0.y * d0.y + f1.x * d0.z + f1.y * d0.w
            + f2.x * d1.x + f2.y * d1.y + f3.x * d1.z + f3.y * d1.w;
#pragma unroll
    for (int o = 4; o >= 1; o >>= 1) {
        s += __shfl_xor_sync(0xFFFFFFFFu, s, o);
        d += __shfl_xor_sync(0xFFFFFFFFu, d, o);
    }
    if ((lane & 7) == 0) {
        int h = lane >> 3;
        ((float*)g_asrc1)[n * 4 + h] = s;
        ((float*)g_adst1)[n * 4 + h] = d;
    }
}

// per-edge logits + CSR scatter fused
__global__ __launch_bounds__(256) void k_edge1(const int* __restrict__ ei,
                                               const float* __restrict__ eattr) {
    __shared__ float v1s[EDIM * HEADS];
    __shared__ float v2s[EDIM];
    if (threadIdx.x < EDIM * HEADS) v1s[threadIdx.x] = g_v1[threadIdx.x];
    if (threadIdx.x < EDIM)         v2s[threadIdx.x] = g_v2[threadIdx.x];
    __syncthreads();
    int e = blockIdx.x * blockDim.x + threadIdx.x;
    if (e >= NE) return;
    int s = ei[e], d = ei[NE + e];
    const float4* ea = (const float4*)(eattr + (size_t)e * EDIM);
    float ae[4] = {0.f, 0.f, 0.f, 0.f};
    float aev2 = 0.f;
#pragma unroll
    for (int j = 0; j < 4; j++) {
        float4 v = ea[j];
        float vals[4] = {v.x, v.y, v.z, v.w};
#pragma unroll
        for (int m = 0; m < 4; m++) {
            int dd = j * 4 + m;
            float ev = vals[m];
#pragma unroll
            for (int h = 0; h < 4; h++) ae[h] = fmaf(ev, v1s[dd * 4 + h], ae[h]);
            aev2 = fmaf(ev, v2s[dd], aev2);
        }
    }
    float4 av = g_asrc1[s], dv = g_adst1[d];
    float4 ex;
    ex.x = __expf(lrelu(av.x + dv.x + ae[0]));
    ex.y = __expf(lrelu(av.y + dv.y + ae[1]));
    ex.z = __expf(lrelu(av.z + dv.z + ae[2]));
    ex.w = __expf(lrelu(av.w + dv.w + ae[3]));
    unsigned pos = atomicAdd(&g_cnt[d], 1u);
    g_csrc[pos] = s;
    g_scr1[pos] = ex;
    g_ae2[pos] = aev2;
}

// layer-1 aggregation: warp per dst node; epilogue bias+relu, fp16 store
__global__ __launch_bounds__(256) void k_agg1(const float* __restrict__ b1) {
    int w = (blockIdx.x * blockDim.x + threadIdx.x) >> 5;
    int lane = threadIdx.x & 31;
    if (w >= NN) return;
    unsigned beg = g_ptr[w], end = g_ptr[w + 1];
    int h = lane >> 3;
    const float* scr = (const float*)g_scr1;
    float a[8] = {0.f, 0.f, 0.f, 0.f, 0.f, 0.f, 0.f, 0.f};
    float ds = 0.f;
    unsigned j = beg;
    for (; j + 2 <= end; j += 2) {
        int s0 = g_csrc[j], s1 = g_csrc[j + 1];
        float x0 = scr[(size_t)j * 4 + h];
        float x1 = scr[(size_t)(j + 1) * 4 + h];
        uint4 v0 = g_h1h[(size_t)s0 * 32 + lane];
        uint4 v1 = g_h1h[(size_t)s1 * 32 + lane];
        ds += x0 + x1;
        float2 f;
        f = h2f(v0.x); a[0] = fmaf(f.x, x0, a[0]); a[1] = fmaf(f.y, x0, a[1]);
        f = h2f(v0.y); a[2] = fmaf(f.x, x0, a[2]); a[3] = fmaf(f.y, x0, a[3]);
        f = h2f(v0.z); a[4] = fmaf(f.x, x0, a[4]); a[5] = fmaf(f.y, x0, a[5]);
        f = h2f(v0.w); a[6] = fmaf(f.x, x0, a[6]); a[7] = fmaf(f.y, x0, a[7]);
        f = h2f(v1.x); a[0] = fmaf(f.x, x1, a[0]); a[1] = fmaf(f.y, x1, a[1]);
        f = h2f(v1.y); a[2] = fmaf(f.x, x1, a[2]); a[3] = fmaf(f.y, x1, a[3]);
        f = h2f(v1.z); a[4] = fmaf(f.x, x1, a[4]); a[5] = fmaf(f.y, x1, a[5]);
        f = h2f(v1.w); a[6] = fmaf(f.x, x1, a[6]); a[7] = fmaf(f.y, x1, a[7]);
    }
    if (j < end) {
        int s0 = g_csrc[j];
        float x0 = scr[(size_t)j * 4 + h];
        uint4 v0 = g_h1h[(size_t)s0 * 32 + lane];
        ds += x0;
        float2 f;
        f = h2f(v0.x); a[0] = fmaf(f.x, x0, a[0]); a[1] = fmaf(f.y, x0, a[1]);
        f = h2f(v0.y); a[2] = fmaf(f.x, x0, a[2]); a[3] = fmaf(f.y, x0, a[3]);
        f = h2f(v0.z); a[4] = fmaf(f.x, x0, a[4]); a[5] = fmaf(f.y, x0, a[5]);
        f = h2f(v0.w); a[6] = fmaf(f.x, x0, a[6]); a[7] = fmaf(f.y, x0, a[7]);
    }
    float inv = 1.f / (ds + 1e-16f);
    float4 b0 = ((const float4*)b1)[2 * lane];
    float4 b1v = ((const float4*)b1)[2 * lane + 1];
    __half2 r0 = __floats2half2_rn(fmaxf(a[0] * inv + b0.x, 0.f),
                                   fmaxf(a[1] * inv + b0.y, 0.f));
    __half2 r1 = __floats2half2_rn(fmaxf(a[2] * inv + b0.z, 0.f),
                                   fmaxf(a[3] * inv + b0.w, 0.f));
    __half2 r2 = __floats2half2_rn(fmaxf(a[4] * inv + b1v.x, 0.f),
                                   fmaxf(a[5] * inv + b1v.y, 0.f));
    __half2 r3 = __floats2half2_rn(fmaxf(a[6] * inv + b1v.z, 0.f),
                                   fmaxf(a[7] * inv + b1v.w, 0.f));
    uint4 pk;
    pk.x = *(unsigned*)&r0; pk.y = *(unsigned*)&r1;
    pk.z = *(unsigned*)&r2; pk.w = *(unsigned*)&r3;
    *reinterpret_cast<uint4*>(&g_out1h[(size_t)w * 128 + lane * 4]) = pk;
}

// ---- h2 = out1 @ W2 via HMMA: block tile 64 nodes x 64 cols, K=256 ----
#define XS2_STRIDE 264                    // 256 + 8 halfs pad
#define WS2_STRIDE 264
#define G2_SMEM ((64 * XS2_STRIDE + 64 * WS2_STRIDE) * 2)

__global__ __launch_bounds__(256) void k_gemm2(const float* __restrict__ W2) {
    extern __shared__ __half sm2[];
    __half* xs = sm2;                     // [64][264]
    __half* ws = sm2 + 64 * XS2_STRIDE;   // [64 n][264 k]
    int t = threadIdx.x;
    int node0 = blockIdx.x * 64;
    // load x tile directly fp16 (g_out1h rows are 256 halfs = 32 uint4)
#pragma unroll
    for (int i = 0; i < 8; i++) {
        int j = i * 256 + t;              // uint4 idx; 32 per row
        int m = j >> 5, q = j & 31;
        uint4 v = make_uint4(0u, 0u, 0u, 0u);
        if (node0 + m < NN)
            v = ((const uint4*)g_out1h)[(size_t)(node0 + m) * 32 + q];
        *(uint4*)&xs[m * XS2_STRIDE + q * 8] = v;
    }
    // load W2 transposed: ws[n][k]
#pragma unroll
    for (int i = 0; i < 16; i++) {
        int j = i * 256 + t;              // 4096 float4
        int k = j >> 4, nq = j & 15;      // 16 float4 per k row
        float4 v = ((const float4*)(W2 + (size_t)k * HID))[nq];
        int n = nq * 4;
        ws[(n + 0) * WS2_STRIDE + k] = __float2half_rn(v.x);
        ws[(n + 1) * WS2_STRIDE + k] = __float2half_rn(v.y);
        ws[(n + 2) * WS2_STRIDE + k] = __float2half_rn(v.z);
        ws[(n + 3) * WS2_STRIDE + k] = __float2half_rn(v.w);
    }
    __syncthreads();
    int warp = t >> 5, lane = t & 31;
    int wm = warp & 3, wn = warp >> 2;    // 4 x 2 warp grid; warp tile 16x32
    int m_base = wm * 16, n_base = wn * 32;
    int r = lane >> 2, kp = (lane & 3) * 2;
    float c[4][4];
#pragma unroll
    for (int j = 0; j < 4; j++)
#pragma unroll
        for (int q = 0; q < 4; q++) c[j][q] = 0.f;
#pragma unroll 4
    for (int k0 = 0; k0 < C1; k0 += 16) {
        unsigned a[4];
        int row = m_base + r;
        a[0] = *(unsigned*)&xs[row * XS2_STRIDE + k0 + kp];
        a[1] = *(unsigned*)&xs[(row + 8) * XS2_STRIDE + k0 + kp];
        a[2] = *(unsigned*)&xs[row * XS2_STRIDE + k0 + 8 + kp];
        a[3] = *(unsigned*)&xs[(row + 8) * XS2_STRIDE + k0 + 8 + kp];
#pragma unroll
        for (int nt = 0; nt < 4; nt++) {
            int n = n_base + nt * 8 + r;
            unsigned b0 = *(unsigned*)&ws[n * WS2_STRIDE + k0 + kp];
            unsigned b1 = *(unsigned*)&ws[n * WS2_STRIDE + k0 + 8 + kp];
            mma16816(c[nt], a, b0, b1);
        }
    }
    __half* h2 = (__half*)g_h2h;
#pragma unroll
    for (int nt = 0; nt < 4; nt++) {
        int row = node0 + m_base + r;
        int col = n_base + nt * 8 + kp;
        if (row < NN)
            *(__half2*)&h2[(size_t)row * HID + col] =
                __floats2half2_rn(c[nt][0], c[nt][1]);
        if (row + 8 < NN)
            *(__half2*)&h2[(size_t)(row + 8) * HID + col] =
                __floats2half2_rn(c[nt][2], c[nt][3]);
    }
}

// layer-2 per-node attention dots (warp per node)
__global__ __launch_bounds__(256) void k_att2(const float* __restrict__ as2,
                                              const float* __restrict__ ad2) {
    int n = (blockIdx.x * blockDim.x + threadIdx.x) >> 5;
    int lane = threadIdx.x & 31;
    if (n >= NN) return;
    float2 f = __half22float2(g_h2h[(size_t)n * 32 + lane]);
    float s = f.x * as2[2 * lane] + f.y * as2[2 * lane + 1];
    float d = f.x * ad2[2 * lane] + f.y * ad2[2 * lane + 1];
#pragma unroll
    for (int o = 16; o >= 1; o >>= 1) {
        s += __shfl_xor_sync(0xFFFFFFFFu, s, o);
        d += __shfl_xor_sync(0xFFFFFFFFu, d, o);
    }
    if (lane == 0) {
        g_asrc2[n] = s;
        g_adst2[n] = d;
    }
}

// layer-2 aggregation + final linear: warp per dst node
__global__ __launch_bounds__(256) void k_agg2(const float* __restrict__ b2,
                                              const float* __restrict__ Wlin,
                                              const float* __restrict__ blin,
                                              float* __restrict__ out) {
    int w = (blockIdx.x * blockDim.x + threadIdx.x) >> 5;
    int lane = threadIdx.x & 31;
    if (w >= NN) return;
    unsigned beg = g_ptr[w], end = g_ptr[w + 1];
    float adw = g_adst2[w];
    float2 acc = make_float2(0.f, 0.f);
    float ds = 0.f;
    unsigned j = beg;
    for (; j + 2 <= end; j += 2) {
        int s0 = g_csrc[j], s1 = g_csrc[j + 1];
        float t0 = g_ae2[j], t1 = g_ae2[j + 1];
        float a0 = g_asrc2[s0], a1 = g_asrc2[s1];
        __half2 v0 = g_h2h[(size_t)s0 * 32 + lane];
        __half2 v1 = g_h2h[(size_t)s1 * 32 + lane];
        float al0 = __expf(lrelu(a0 + adw + t0));
        float al1 = __expf(lrelu(a1 + adw + t1));
        ds += al0 + al1;
        float2 f0 = __half22float2(v0), f1 = __half22float2(v1);
        acc.x = fmaf(f0.x, al0, acc.x); acc.y = fmaf(f0.y, al0, acc.y);
        acc.x = fmaf(f1.x, al1, acc.x); acc.y = fmaf(f1.y, al1, acc.y);
    }
    if (j < end) {
        int s0 = g_csrc[j];
        float al0 = __expf(lrelu(g_asrc2[s0] + adw + g_ae2[j]));
        ds += al0;
        float2 f0 = __half22float2(g_h2h[(size_t)s0 * 32 + lane]);
        acc.x = fmaf(f0.x, al0, acc.x); acc.y = fmaf(f0.y, al0, acc.y);
    }
    float inv = 1.f / (ds + 1e-16f);
    float v0 = fmaxf(acc.x * inv + b2[2 * lane], 0.f);
    float v1 = fmaxf(acc.y * inv + b2[2 * lane + 1], 0.f);
    float r = v0 * Wlin[2 * lane] + v1 * Wlin[2 * lane + 1];
#pragma unroll
    for (int o = 16; o >= 1; o >>= 1) r += __shfl_xor_sync(0xFFFFFFFFu, r, o);
    if (lane == 0) out[w] = r + blin[0];
}

// ---------------- launch ----------------
extern "C" void kernel_launch(void* const* d_in, const int* in_sizes, int n_in,
                              void* d_out, int out_size) {
    const float* x     = (const float*)d_in[0];
    const int*   ei    = (const int*)d_in[1];
    const float* eattr = (const float*)d_in[2];
    const float* W1    = (const float*)d_in[3];
    const float* We1   = (const float*)d_in[4];
    const float* as1   = (const float*)d_in[5];
    const float* ad1   = (const float*)d_in[6];
    const float* ae1   = (const float*)d_in[7];
    const float* b1    = (const float*)d_in[8];
    const float* W2    = (const float*)d_in[9];
    const float* We2   = (const float*)d_in[10];
    const float* as2   = (const float*)d_in[11];
    const float* ad2   = (const float*)d_in[12];
    const float* ae2   = (const float*)d_in[13];
    const float* b2    = (const float*)d_in[14];
    const float* Wlin  = (const float*)d_in[15];
    const float* blin  = (const float*)d_in[16];
    float* out = (float*)d_out;

    static bool attr_done = false;
    if (!attr_done) {
        cudaFuncSetAttribute(k_gemm1, cudaFuncAttributeMaxDynamicSharedMemorySize, G1_SMEM);
        cudaFuncSetAttribute(k_gemm2, cudaFuncAttributeMaxDynamicSharedMemorySize, G2_SMEM);
        attr_done = true;
    }

    k_init<<<(NN + 255) / 256, 256>>>(We1, ae1, We2, ae2);
    k_hist<<<NE / 256, 256>>>(ei);
    k_scan<<<1, 1024>>>();
    k_gemm1<<<dim3((NN + 63) / 64, 2), 256, G1_SMEM>>>(x, W1);
    k_att1<<<(NN * 32 + 255) / 256, 256>>>(as1, ad1);
    k_edge1<<<NE / 256, 256>>>(ei, eattr);
    k_agg1<<<(NN * 32 + 255) / 256, 256>>>(b1);
    k_gemm2<<<(NN + 63) / 64, 256, G2_SMEM>>>(W2);
    k_att2<<<(NN * 32 + 255) / 256, 256>>>(as2, ad2);
    k_agg2<<<(NN * 32 + 255) / 256, 256>>>(b2, Wlin, blin, out);
}

// round 7
// speedup vs baseline: 1.8005x; 1.2310x over previous
#include <cuda_runtime.h>
#include <cuda_fp16.h>

#define NN 50000
#define NE 800000
#define IND 128
#define HID 64
#define HEADS 4
#define C1 256            // HEADS*HID
#define EDIM 16

// ---------------- scratch (device globals) ----------------
__device__ uint4    g_h1h[NN * 32];         // [N,256] h1, fp16
__device__ __half2  g_out1h[NN * 128];      // [N,256] relu(agg1+b1), fp16
__device__ __half2  g_h2h[NN * 32];         // [N,64]  h2, fp16
__device__ __half   g_w1t[C1 * IND];        // W1^T fp16 [256 n][128 k]
__device__ __half   g_w2t[HID * C1];        // W2^T fp16 [64 n][256 k]
__device__ float4   g_scr1[NE];             // exp(logits) 4 heads, AT CSR POS
__device__ float    g_ae2[NE];              // layer-2 edge term, AT CSR POS
__device__ int      g_csrc[NE];             // src node, AT CSR POS
__device__ float4   g_asrc1[NN], g_adst1[NN];
__device__ float    g_asrc2[NN], g_adst2[NN];
__device__ float    g_v1[EDIM * HEADS];
__device__ float    g_v2[EDIM];
__device__ unsigned g_deg[NN];
__device__ unsigned g_cnt[NN];
__device__ unsigned g_ptr[NN + 1];

// ---------------- helpers ----------------
__device__ __forceinline__ float lrelu(float x) { return x > 0.f ? x : 0.2f * x; }
__device__ __forceinline__ float2 h2f(unsigned u) {
    return __half22float2(*reinterpret_cast<__half2*>(&u));
}
__device__ __forceinline__ void mma16816(float* c, const unsigned* a,
                                         unsigned b0, unsigned b1) {
    asm volatile(
        "mma.sync.aligned.m16n8k16.row.col.f32.f16.f16.f32 "
        "{%0,%1,%2,%3}, {%4,%5,%6,%7}, {%8,%9}, {%0,%1,%2,%3};"
        : "+f"(c[0]), "+f"(c[1]), "+f"(c[2]), "+f"(c[3])
        : "r"(a[0]), "r"(a[1]), "r"(a[2]), "r"(a[3]), "r"(b0), "r"(b1));
}
__device__ __forceinline__ void ldsm4(unsigned* r, unsigned addr) {
    asm volatile("ldmatrix.sync.aligned.m8n8.x4.shared.b16 {%0,%1,%2,%3}, [%4];"
                 : "=r"(r[0]), "=r"(r[1]), "=r"(r[2]), "=r"(r[3]) : "r"(addr));
}

// ---------------- kernels ----------------
// zero degree, transpose+convert weights, collapse edge-attention vecs
__global__ __launch_bounds__(256) void k_init(const float* __restrict__ We1,
                                              const float* __restrict__ ae1,
                                              const float* __restrict__ We2,
                                              const float* __restrict__ ae2,
                                              const float* __restrict__ W1,
                                              const float* __restrict__ W2) {
    int i = blockIdx.x * blockDim.x + threadIdx.x;
    if (i < NN) g_deg[i] = 0u;
    // W1^T: 32768 elems; W2^T: 16384 elems
    if (i < C1 * IND) {
        int n = i >> 7, k = i & 127;
        g_w1t[i] = __float2half_rn(W1[k * C1 + n]);
    }
    if (i < HID * C1) {
        int n = i >> 8, k = i & 255;
        g_w2t[i] = __float2half_rn(W2[k * HID + n]);
    }
    if (blockIdx.x == 0) {
        int t = threadIdx.x;
        if (t < EDIM * HEADS) {
            int d = t >> 2, h = t & 3;
            float s = 0.f;
            for (int c = 0; c < HID; c++) s += We1[d * C1 + h * HID + c] * ae1[h * HID + c];
            g_v1[t] = s;
        }
        if (t < EDIM) {
            float s = 0.f;
            for (int c = 0; c < HID; c++) s += We2[t * HID + c] * ae2[c];
            g_v2[t] = s;
        }
    }
}

__global__ __launch_bounds__(256) void k_hist(const int* __restrict__ ei) {
    int e = blockIdx.x * blockDim.x + threadIdx.x;
    if (e < NE) atomicAdd(&g_deg[ei[NE + e]], 1u);
}

// single-block exclusive scan of degrees -> g_ptr, g_cnt
__global__ __launch_bounds__(1024) void k_scan() {
    __shared__ unsigned wsum[32];
    const int T = 1024;
    int t = threadIdx.x;
    int per = (NN + T - 1) / T;
    int b = t * per, e = min(b + per, NN);
    unsigned s = 0;
    for (int i = b; i < e; i++) s += g_deg[i];
    unsigned lane = t & 31, wid = t >> 5;
    unsigned incl = s;
#pragma unroll
    for (int o = 1; o < 32; o <<= 1) {
        unsigned u = __shfl_up_sync(0xFFFFFFFFu, incl, o);
        if (lane >= (unsigned)o) incl += u;
    }
    if (lane == 31) wsum[wid] = incl;
    __syncthreads();
    if (wid == 0) {
        unsigned v = wsum[lane];
        unsigned vi = v;
#pragma unroll
        for (int o = 1; o < 32; o <<= 1) {
            unsigned u = __shfl_up_sync(0xFFFFFFFFu, vi, o);
            if (lane >= (unsigned)o) vi += u;
        }
        wsum[lane] = vi - v;
    }
    __syncthreads();
    unsigned run = incl - s + wsum[wid];
    for (int i = b; i < e; i++) {
        unsigned d = g_deg[i];
        g_ptr[i] = run;
        g_cnt[i] = run;
        run += d;
    }
    if (t == T - 1) g_ptr[NN] = NE;
}

// ---- h1 = x @ W1 via HMMA+LDSM: block tile 64 nodes x 128 cols ----
#define XS1_STRIDE 136                    // 128 + 8 halfs pad
#define WS1_STRIDE 136
#define G1_SMEM ((64 * XS1_STRIDE + 128 * WS1_STRIDE) * 2)

__global__ __launch_bounds__(256) void k_gemm1(const float* __restrict__ x) {
    extern __shared__ __half sm1[];
    __half* xs = sm1;                     // [64 m][136 k]
    __half* ws = sm1 + 64 * XS1_STRIDE;   // [128 n][136 k]
    int t = threadIdx.x;
    int node0 = blockIdx.x * 64;
    int ncol0 = blockIdx.y * 128;
    // x tile (fp32 -> fp16)
#pragma unroll
    for (int i = 0; i < 8; i++) {
        int j = i * 256 + t;              // float4 idx; 32 per row
        int m = j >> 5, kq = j & 31;
        float4 v = make_float4(0.f, 0.f, 0.f, 0.f);
        if (node0 + m < NN) v = ((const float4*)x)[(size_t)(node0 + m) * 32 + kq];
        *(__half2*)&xs[m * XS1_STRIDE + kq * 4]     = __floats2half2_rn(v.x, v.y);
        *(__half2*)&xs[m * XS1_STRIDE + kq * 4 + 2] = __floats2half2_rn(v.z, v.w);
    }
    // W tile: direct fp16 vector copy from pre-transposed g_w1t
#pragma unroll
    for (int i = 0; i < 8; i++) {
        int j = i * 256 + t;              // uint4 idx: 128 rows x 16
        int n = j >> 4, q = j & 15;
        uint4 v = ((const uint4*)(g_w1t + (size_t)(ncol0 + n) * IND))[q];
        *(uint4*)&ws[n * WS1_STRIDE + q * 8] = v;
    }
    __syncthreads();
    int warp = t >> 5, lane = t & 31;
    int wm = warp & 1, wn = warp >> 1;    // 2 x 4 warp grid; warp tile 32x32
    int m_base = wm * 32, n_base = wn * 32;
    unsigned xs_sa = (unsigned)__cvta_generic_to_shared(xs);
    unsigned ws_sa = (unsigned)__cvta_generic_to_shared(ws);
    unsigned aA = xs_sa + ((m_base + ((lane >> 3) & 1) * 8 + (lane & 7)) * XS1_STRIDE
                           + (lane >> 4) * 8) * 2;
    unsigned aB = ws_sa + ((n_base + (lane >> 4) * 8 + (lane & 7)) * WS1_STRIDE
                           + ((lane >> 3) & 1) * 8) * 2;
    float c[2][4][4];
#pragma unroll
    for (int i = 0; i < 2; i++)
#pragma unroll
        for (int j = 0; j < 4; j++)
#pragma unroll
            for (int q = 0; q < 4; q++) c[i][j][q] = 0.f;
#pragma unroll
    for (int k0 = 0; k0 < IND; k0 += 16) {
        unsigned a0[4], a1[4], b0[4], b1[4];
        ldsm4(a0, aA + k0 * 2);
        ldsm4(a1, aA + (16 * XS1_STRIDE + k0) * 2);
        ldsm4(b0, aB + k0 * 2);
        ldsm4(b1, aB + (16 * WS1_STRIDE + k0) * 2);
        mma16816(c[0][0], a0, b0[0], b0[1]);
        mma16816(c[0][1], a0, b0[2], b0[3]);
        mma16816(c[0][2], a0, b1[0], b1[1]);
        mma16816(c[0][3], a0, b1[2], b1[3]);
        mma16816(c[1][0], a1, b0[0], b0[1]);
        mma16816(c[1][1], a1, b0[2], b0[3]);
        mma16816(c[1][2], a1, b1[0], b1[1]);
        mma16816(c[1][3], a1, b1[2], b1[3]);
    }
    int r = lane >> 2, kp = (lane & 3) * 2;
    __half* h1 = (__half*)g_h1h;
#pragma unroll
    for (int mt = 0; mt < 2; mt++) {
#pragma unroll
        for (int nt = 0; nt < 4; nt++) {
            int row = node0 + m_base + mt * 16 + r;
            int col = ncol0 + n_base + nt * 8 + kp;
            if (row < NN)
                *(__half2*)&h1[(size_t)row * C1 + col] =
                    __floats2half2_rn(c[mt][nt][0], c[mt][nt][1]);
            if (row + 8 < NN)
                *(__half2*)&h1[(size_t)(row + 8) * C1 + col] =
                    __floats2half2_rn(c[mt][nt][2], c[mt][nt][3]);
        }
    }
}

// per-node attention dots from fp16 h1 (warp per node)
__global__ __launch_bounds__(256) void k_att1(const float* __restrict__ as1,
                                              const float* __restrict__ ad1) {
    int n = (blockIdx.x * blockDim.x + threadIdx.x) >> 5;
    int lane = threadIdx.x & 31;
    if (n >= NN) return;
    uint4 hv = g_h1h[(size_t)n * 32 + lane];
    float4 a0 = ((const float4*)as1)[2 * lane], a1 = ((const float4*)as1)[2 * lane + 1];
    float4 d0 = ((const float4*)ad1)[2 * lane], d1 = ((const float4*)ad1)[2 * lane + 1];
    float2 f0 = h2f(hv.x), f1 = h2f(hv.y), f2 = h2f(hv.z), f3 = h2f(hv.w);
    float s = f0.x * a0.x + f0.y * a0.y + f1.x * a0.z + f1.y * a0.w
            + f2.x * a1.x + f2.y * a1.y + f3.x * a1.z + f3.y * a1.w;
    float d = f0.x * d0.x + f0.y * d0.y + f1.x * d0.z + f1.y * d0.w
            + f2.x * d1.x + f2.y * d1.y + f3.x * d1.z + f3.y * d1.w;
#pragma unroll
    for (int o = 4; o >= 1; o >>= 1) {
        s += __shfl_xor_sync(0xFFFFFFFFu, s, o);
        d += __shfl_xor_sync(0xFFFFFFFFu, d, o);
    }
    if ((lane & 7) == 0) {
        int h = lane >> 3;
        ((float*)g_asrc1)[n * 4 + h] = s;
        ((float*)g_adst1)[n * 4 + h] = d;
    }
}

// per-edge logits + CSR scatter fused
__global__ __launch_bounds__(256) void k_edge1(const int* __restrict__ ei,
                                               const float* __restrict__ eattr) {
    __shared__ float v1s[EDIM * HEADS];
    __shared__ float v2s[EDIM];
    if (threadIdx.x < EDIM * HEADS) v1s[threadIdx.x] = g_v1[threadIdx.x];
    if (threadIdx.x < EDIM)         v2s[threadIdx.x] = g_v2[threadIdx.x];
    __syncthreads();
    int e = blockIdx.x * blockDim.x + threadIdx.x;
    if (e >= NE) return;
    int s = ei[e], d = ei[NE + e];
    const float4* ea = (const float4*)(eattr + (size_t)e * EDIM);
    float ae[4] = {0.f, 0.f, 0.f, 0.f};
    float aev2 = 0.f;
#pragma unroll
    for (int j = 0; j < 4; j++) {
        float4 v = ea[j];
        float vals[4] = {v.x, v.y, v.z, v.w};
#pragma unroll
        for (int m = 0; m < 4; m++) {
            int dd = j * 4 + m;
            float ev = vals[m];
#pragma unroll
            for (int h = 0; h < 4; h++) ae[h] = fmaf(ev, v1s[dd * 4 + h], ae[h]);
            aev2 = fmaf(ev, v2s[dd], aev2);
        }
    }
    float4 av = g_asrc1[s], dv = g_adst1[d];
    float4 ex;
    ex.x = __expf(lrelu(av.x + dv.x + ae[0]));
    ex.y = __expf(lrelu(av.y + dv.y + ae[1]));
    ex.z = __expf(lrelu(av.z + dv.z + ae[2]));
    ex.w = __expf(lrelu(av.w + dv.w + ae[3]));
    unsigned pos = atomicAdd(&g_cnt[d], 1u);
    g_csrc[pos] = s;
    g_scr1[pos] = ex;
    g_ae2[pos] = aev2;
}

// layer-1 aggregation: warp per dst node; epilogue bias+relu, fp16 store
__global__ __launch_bounds__(256) void k_agg1(const float* __restrict__ b1) {
    int w = (blockIdx.x * blockDim.x + threadIdx.x) >> 5;
    int lane = threadIdx.x & 31;
    if (w >= NN) return;
    unsigned beg = g_ptr[w], end = g_ptr[w + 1];
    int h = lane >> 3;
    const float* scr = (const float*)g_scr1;
    float a[8] = {0.f, 0.f, 0.f, 0.f, 0.f, 0.f, 0.f, 0.f};
    float ds = 0.f;
    unsigned j = beg;
    for (; j + 2 <= end; j += 2) {
        int s0 = g_csrc[j], s1 = g_csrc[j + 1];
        float x0 = scr[(size_t)j * 4 + h];
        float x1 = scr[(size_t)(j + 1) * 4 + h];
        uint4 v0 = g_h1h[(size_t)s0 * 32 + lane];
        uint4 v1 = g_h1h[(size_t)s1 * 32 + lane];
        ds += x0 + x1;
        float2 f;
        f = h2f(v0.x); a[0] = fmaf(f.x, x0, a[0]); a[1] = fmaf(f.y, x0, a[1]);
        f = h2f(v0.y); a[2] = fmaf(f.x, x0, a[2]); a[3] = fmaf(f.y, x0, a[3]);
        f = h2f(v0.z); a[4] = fmaf(f.x, x0, a[4]); a[5] = fmaf(f.y, x0, a[5]);
        f = h2f(v0.w); a[6] = fmaf(f.x, x0, a[6]); a[7] = fmaf(f.y, x0, a[7]);
        f = h2f(v1.x); a[0] = fmaf(f.x, x1, a[0]); a[1] = fmaf(f.y, x1, a[1]);
        f = h2f(v1.y); a[2] = fmaf(f.x, x1, a[2]); a[3] = fmaf(f.y, x1, a[3]);
        f = h2f(v1.z); a[4] = fmaf(f.x, x1, a[4]); a[5] = fmaf(f.y, x1, a[5]);
        f = h2f(v1.w); a[6] = fmaf(f.x, x1, a[6]); a[7] = fmaf(f.y, x1, a[7]);
    }
    if (j < end) {
        int s0 = g_csrc[j];
        float x0 = scr[(size_t)j * 4 + h];
        uint4 v0 = g_h1h[(size_t)s0 * 32 + lane];
        ds += x0;
        float2 f;
        f = h2f(v0.x); a[0] = fmaf(f.x, x0, a[0]); a[1] = fmaf(f.y, x0, a[1]);
        f = h2f(v0.y); a[2] = fmaf(f.x, x0, a[2]); a[3] = fmaf(f.y, x0, a[3]);
        f = h2f(v0.z); a[4] = fmaf(f.x, x0, a[4]); a[5] = fmaf(f.y, x0, a[5]);
        f = h2f(v0.w); a[6] = fmaf(f.x, x0, a[6]); a[7] = fmaf(f.y, x0, a[7]);
    }
    float inv = 1.f / (ds + 1e-16f);
    float4 b0 = ((const float4*)b1)[2 * lane];
    float4 b1v = ((const float4*)b1)[2 * lane + 1];
    __half2 r0 = __floats2half2_rn(fmaxf(a[0] * inv + b0.x, 0.f),
                                   fmaxf(a[1] * inv + b0.y, 0.f));
    __half2 r1 = __floats2half2_rn(fmaxf(a[2] * inv + b0.z, 0.f),
                                   fmaxf(a[3] * inv + b0.w, 0.f));
    __half2 r2 = __floats2half2_rn(fmaxf(a[4] * inv + b1v.x, 0.f),
                                   fmaxf(a[5] * inv + b1v.y, 0.f));
    __half2 r3 = __floats2half2_rn(fmaxf(a[6] * inv + b1v.z, 0.f),
                                   fmaxf(a[7] * inv + b1v.w, 0.f));
    uint4 pk;
    pk.x = *(unsigned*)&r0; pk.y = *(unsigned*)&r1;
    pk.z = *(unsigned*)&r2; pk.w = *(unsigned*)&r3;
    *reinterpret_cast<uint4*>(&g_out1h[(size_t)w * 128 + lane * 4]) = pk;
}

// ---- h2 = out1 @ W2 via HMMA+LDSM: block tile 64 nodes x 64 cols, K=256 ----
#define XS2_STRIDE 264                    // 256 + 8 halfs pad
#define WS2_STRIDE 264
#define G2_SMEM ((64 * XS2_STRIDE + 64 * WS2_STRIDE) * 2)

__global__ __launch_bounds__(256) void k_gemm2() {
    extern __shared__ __half sm2[];
    __half* xs = sm2;                     // [64 m][264 k]
    __half* ws = sm2 + 64 * XS2_STRIDE;   // [64 n][264 k]
    int t = threadIdx.x;
    int node0 = blockIdx.x * 64;
    // x tile: direct fp16 copy (rows are 256 halfs = 32 uint4)
#pragma unroll
    for (int i = 0; i < 8; i++) {
        int j = i * 256 + t;
        int m = j >> 5, q = j & 31;
        uint4 v = make_uint4(0u, 0u, 0u, 0u);
        if (node0 + m < NN)
            v = ((const uint4*)g_out1h)[(size_t)(node0 + m) * 32 + q];
        *(uint4*)&xs[m * XS2_STRIDE + q * 8] = v;
    }
    // W tile: direct fp16 copy from pre-transposed g_w2t [64 n][256 k]
#pragma unroll
    for (int i = 0; i < 8; i++) {
        int j = i * 256 + t;
        int n = j >> 5, q = j & 31;
        uint4 v = ((const uint4*)(g_w2t + (size_t)n * C1))[q];
        *(uint4*)&ws[n * WS2_STRIDE + q * 8] = v;
    }
    __syncthreads();
    int warp = t >> 5, lane = t & 31;
    int wm = warp & 3, wn = warp >> 2;    // 4 x 2 warp grid; warp tile 16x32
    int m_base = wm * 16, n_base = wn * 32;
    unsigned xs_sa = (unsigned)__cvta_generic_to_shared(xs);
    unsigned ws_sa = (unsigned)__cvta_generic_to_shared(ws);
    unsigned aA = xs_sa + ((m_base + ((lane >> 3) & 1) * 8 + (lane & 7)) * XS2_STRIDE
                           + (lane >> 4) * 8) * 2;
    unsigned aB = ws_sa + ((n_base + (lane >> 4) * 8 + (lane & 7)) * WS2_STRIDE
                           + ((lane >> 3) & 1) * 8) * 2;
    float c[4][4];
#pragma unroll
    for (int j = 0; j < 4; j++)
#pragma unroll
        for (int q = 0; q < 4; q++) c[j][q] = 0.f;
#pragma unroll
    for (int k0 = 0; k0 < C1; k0 += 16) {
        unsigned a[4], b0[4], b1[4];
        ldsm4(a, aA + k0 * 2);
        ldsm4(b0, aB + k0 * 2);
        ldsm4(b1, aB + (16 * WS2_STRIDE + k0) * 2);
        mma16816(c[0], a, b0[0], b0[1]);
        mma16816(c[1], a, b0[2], b0[3]);
        mma16816(c[2], a, b1[0], b1[1]);
        mma16816(c[3], a, b1[2], b1[3]);
    }
    int r = lane >> 2, kp = (lane & 3) * 2;
    __half* h2 = (__half*)g_h2h;
#pragma unroll
    for (int nt = 0; nt < 4; nt++) {
        int row = node0 + m_base + r;
        int col = n_base + nt * 8 + kp;
        if (row < NN)
            *(__half2*)&h2[(size_t)row * HID + col] =
                __floats2half2_rn(c[nt][0], c[nt][1]);
        if (row + 8 < NN)
            *(__half2*)&h2[(size_t)(row + 8) * HID + col] =
                __floats2half2_rn(c[nt][2], c[nt][3]);
    }
}

// layer-2 per-node attention dots (warp per node)
__global__ __launch_bounds__(256) void k_att2(const float* __restrict__ as2,
                                              const float* __restrict__ ad2) {
    int n = (blockIdx.x * blockDim.x + threadIdx.x) >> 5;
    int lane = threadIdx.x & 31;
    if (n >= NN) return;
    float2 f = __half22float2(g_h2h[(size_t)n * 32 + lane]);
    float s = f.x * as2[2 * lane] + f.y * as2[2 * lane + 1];
    float d = f.x * ad2[2 * lane] + f.y * ad2[2 * lane + 1];
#pragma unroll
    for (int o = 16; o >= 1; o >>= 1) {
        s += __shfl_xor_sync(0xFFFFFFFFu, s, o);
        d += __shfl_xor_sync(0xFFFFFFFFu, d, o);
    }
    if (lane == 0) {
        g_asrc2[n] = s;
        g_adst2[n] = d;
    }
}

// layer-2 aggregation + final linear: warp per dst node
__global__ __launch_bounds__(256) void k_agg2(const float* __restrict__ b2,
                                              const float* __restrict__ Wlin,
                                              const float* __restrict__ blin,
                                              float* __restrict__ out) {
    int w = (blockIdx.x * blockDim.x + threadIdx.x) >> 5;
    int lane = threadIdx.x & 31;
    if (w >= NN) return;
    unsigned beg = g_ptr[w], end = g_ptr[w + 1];
    float adw = g_adst2[w];
    float2 acc = make_float2(0.f, 0.f);
    float ds = 0.f;
    unsigned j = beg;
    for (; j + 2 <= end; j += 2) {
        int s0 = g_csrc[j], s1 = g_csrc[j + 1];
        float t0 = g_ae2[j], t1 = g_ae2[j + 1];
        float a0 = g_asrc2[s0], a1 = g_asrc2[s1];
        __half2 v0 = g_h2h[(size_t)s0 * 32 + lane];
        __half2 v1 = g_h2h[(size_t)s1 * 32 + lane];
        float al0 = __expf(lrelu(a0 + adw + t0));
        float al1 = __expf(lrelu(a1 + adw + t1));
        ds += al0 + al1;
        float2 f0 = __half22float2(v0), f1 = __half22float2(v1);
        acc.x = fmaf(f0.x, al0, acc.x); acc.y = fmaf(f0.y, al0, acc.y);
        acc.x = fmaf(f1.x, al1, acc.x); acc.y = fmaf(f1.y, al1, acc.y);
    }
    if (j < end) {
        int s0 = g_csrc[j];
        float al0 = __expf(lrelu(g_asrc2[s0] + adw + g_ae2[j]));
        ds += al0;
        float2 f0 = __half22float2(g_h2h[(size_t)s0 * 32 + lane]);
        acc.x = fmaf(f0.x, al0, acc.x); acc.y = fmaf(f0.y, al0, acc.y);
    }
    float inv = 1.f / (ds + 1e-16f);
    float v0 = fmaxf(acc.x * inv + b2[2 * lane], 0.f);
    float v1 = fmaxf(acc.y * inv + b2[2 * lane + 1], 0.f);
    float r = v0 * Wlin[2 * lane] + v1 * Wlin[2 * lane + 1];
#pragma unroll
    for (int o = 16; o >= 1; o >>= 1) r += __shfl_xor_sync(0xFFFFFFFFu, r, o);
    if (lane == 0) out[w] = r + blin[0];
}

// ---------------- launch ----------------
extern "C" void kernel_launch(void* const* d_in, const int* in_sizes, int n_in,
                              void* d_out, int out_size) {
    const float* x     = (const float*)d_in[0];
    const int*   ei    = (const int*)d_in[1];
    const float* eattr = (const float*)d_in[2];
    const float* W1    = (const float*)d_in[3];
    const float* We1   = (const float*)d_in[4];
    const float* as1   = (const float*)d_in[5];
    const float* ad1   = (const float*)d_in[6];
    const float* ae1   = (const float*)d_in[7];
    const float* b1    = (const float*)d_in[8];
    const float* W2    = (const float*)d_in[9];
    const float* We2   = (const float*)d_in[10];
    const float* as2   = (const float*)d_in[11];
    const float* ad2   = (const float*)d_in[12];
    const float* ae2   = (const float*)d_in[13];
    const float* b2    = (const float*)d_in[14];
    const float* Wlin  = (const float*)d_in[15];
    const float* blin  = (const float*)d_in[16];
    float* out = (float*)d_out;

    static bool attr_done = false;
    if (!attr_done) {
        cudaFuncSetAttribute(k_gemm1, cudaFuncAttributeMaxDynamicSharedMemorySize, G1_SMEM);
        cudaFuncSetAttribute(k_gemm2, cudaFuncAttributeMaxDynamicSharedMemorySize, G2_SMEM);
        attr_done = true;
    }

    k_init<<<(NN + 255) / 256, 256>>>(We1, ae1, We2, ae2, W1, W2);
    k_hist<<<NE / 256, 256>>>(ei);
    k_scan<<<1, 1024>>>();
    k_gemm1<<<dim3((NN + 63) / 64, 2), 256, G1_SMEM>>>(x);
    k_att1<<<(NN * 32 + 255) / 256, 256>>>(as1, ad1);
    k_edge1<<<NE / 256, 256>>>(ei, eattr);
    k_agg1<<<(NN * 32 + 255) / 256, 256>>>(b1);
    k_gemm2<<<(NN + 63) / 64, 256, G2_SMEM>>>();
    k_att2<<<(NN * 32 + 255) / 256, 256>>>(as2, ad2);
    k_agg2<<<(NN * 32 + 255) / 256, 256>>>(b2, Wlin, blin, out);
}

// round 8
// speedup vs baseline: 1.8949x; 1.0524x over previous
#include <cuda_runtime.h>
#include <cuda_fp16.h>

#define NN 50000
#define NE 800000
#define IND 128
#define HID 64
#define HEADS 4
#define C1 256            // HEADS*HID
#define EDIM 16

// ---------------- scratch (device globals) ----------------
__device__ uint4    g_h1h[NN * 32];         // [N,256] h1, fp16
__device__ __half2  g_out1h[NN * 128];      // [N,256] relu(agg1+b1), fp16
__device__ __half2  g_h2h[NN * 32];         // [N,64]  h2, fp16
__device__ __half   g_w1t[C1 * IND];        // W1^T fp16 [256 n][128 k]
__device__ __half   g_w2t[HID * C1];        // W2^T fp16 [64 n][256 k]
__device__ float4   g_scr1[NE];             // exp(logits) 4 heads, AT CSR POS
__device__ int2     g_misc[NE];             // (src, ae2-bits), AT CSR POS
__device__ float4   g_asrc1[NN], g_adst1[NN];
__device__ float    g_asrc2[NN], g_adst2[NN];
__device__ float    g_v1[EDIM * HEADS];
__device__ float    g_v2[EDIM];
__device__ unsigned g_deg[NN];
__device__ unsigned g_cnt[NN];
__device__ unsigned g_ptr[NN + 1];

// ---------------- helpers ----------------
__device__ __forceinline__ float lrelu(float x) { return x > 0.f ? x : 0.2f * x; }
__device__ __forceinline__ float2 h2f(unsigned u) {
    return __half22float2(*reinterpret_cast<__half2*>(&u));
}
__device__ __forceinline__ void mma16816(float* c, const unsigned* a,
                                         unsigned b0, unsigned b1) {
    asm volatile(
        "mma.sync.aligned.m16n8k16.row.col.f32.f16.f16.f32 "
        "{%0,%1,%2,%3}, {%4,%5,%6,%7}, {%8,%9}, {%0,%1,%2,%3};"
        : "+f"(c[0]), "+f"(c[1]), "+f"(c[2]), "+f"(c[3])
        : "r"(a[0]), "r"(a[1]), "r"(a[2]), "r"(a[3]), "r"(b0), "r"(b1));
}
__device__ __forceinline__ void ldsm4(unsigned* r, unsigned addr) {
    asm volatile("ldmatrix.sync.aligned.m8n8.x4.shared.b16 {%0,%1,%2,%3}, [%4];"
                 : "=r"(r[0]), "=r"(r[1]), "=r"(r[2]), "=r"(r[3]) : "r"(addr));
}

// ---------------- kernels ----------------
// zero counters/accumulators, transpose+convert weights, collapse edge vecs
__global__ __launch_bounds__(256) void k_init(const float* __restrict__ We1,
                                              const float* __restrict__ ae1,
                                              const float* __restrict__ We2,
                                              const float* __restrict__ ae2,
                                              const float* __restrict__ W1,
                                              const float* __restrict__ W2) {
    int i = blockIdx.x * blockDim.x + threadIdx.x;
    if (i < NN) {
        g_deg[i] = 0u;
        float4 z = make_float4(0.f, 0.f, 0.f, 0.f);
        g_asrc1[i] = z; g_adst1[i] = z;
        g_asrc2[i] = 0.f; g_adst2[i] = 0.f;
    }
    if (i < C1 * IND) {
        int n = i >> 7, k = i & 127;
        g_w1t[i] = __float2half_rn(W1[k * C1 + n]);
    }
    if (i < HID * C1) {
        int n = i >> 8, k = i & 255;
        g_w2t[i] = __float2half_rn(W2[k * HID + n]);
    }
    if (blockIdx.x == 0) {
        int t = threadIdx.x;
        if (t < EDIM * HEADS) {
            int d = t >> 2, h = t & 3;
            float s = 0.f;
            for (int c = 0; c < HID; c++) s += We1[d * C1 + h * HID + c] * ae1[h * HID + c];
            g_v1[t] = s;
        }
        if (t < EDIM) {
            float s = 0.f;
            for (int c = 0; c < HID; c++) s += We2[t * HID + c] * ae2[c];
            g_v2[t] = s;
        }
    }
}

__global__ __launch_bounds__(256) void k_hist(const int* __restrict__ ei) {
    int e = blockIdx.x * blockDim.x + threadIdx.x;
    if (e < NE) atomicAdd(&g_deg[ei[NE + e]], 1u);
}

// single-block exclusive scan of degrees -> g_ptr, g_cnt
__global__ __launch_bounds__(1024) void k_scan() {
    __shared__ unsigned wsum[32];
    const int T = 1024;
    int t = threadIdx.x;
    int per = (NN + T - 1) / T;
    int b = t * per, e = min(b + per, NN);
    unsigned s = 0;
    for (int i = b; i < e; i++) s += g_deg[i];
    unsigned lane = t & 31, wid = t >> 5;
    unsigned incl = s;
#pragma unroll
    for (int o = 1; o < 32; o <<= 1) {
        unsigned u = __shfl_up_sync(0xFFFFFFFFu, incl, o);
        if (lane >= (unsigned)o) incl += u;
    }
    if (lane == 31) wsum[wid] = incl;
    __syncthreads();
    if (wid == 0) {
        unsigned v = wsum[lane];
        unsigned vi = v;
#pragma unroll
        for (int o = 1; o < 32; o <<= 1) {
            unsigned u = __shfl_up_sync(0xFFFFFFFFu, vi, o);
            if (lane >= (unsigned)o) vi += u;
        }
        wsum[lane] = vi - v;
    }
    __syncthreads();
    unsigned run = incl - s + wsum[wid];
    for (int i = b; i < e; i++) {
        unsigned d = g_deg[i];
        g_ptr[i] = run;
        g_cnt[i] = run;
        run += d;
    }
    if (t == T - 1) g_ptr[NN] = NE;
}

// ---- h1 = x @ W1 via HMMA+LDSM, att1 dots fused in epilogue ----
#define XS1_STRIDE 136
#define WS1_STRIDE 136
#define G1_SMEM ((64 * XS1_STRIDE + 128 * WS1_STRIDE) * 2)

__global__ __launch_bounds__(256) void k_gemm1(const float* __restrict__ x,
                                               const float* __restrict__ as1,
                                               const float* __restrict__ ad1) {
    extern __shared__ __half sm1[];
    __half* xs = sm1;                     // [64 m][136 k]
    __half* ws = sm1 + 64 * XS1_STRIDE;   // [128 n][136 k]
    int t = threadIdx.x;
    int node0 = blockIdx.x * 64;
    int ncol0 = blockIdx.y * 128;
#pragma unroll
    for (int i = 0; i < 8; i++) {
        int j = i * 256 + t;
        int m = j >> 5, kq = j & 31;
        float4 v = make_float4(0.f, 0.f, 0.f, 0.f);
        if (node0 + m < NN) v = ((const float4*)x)[(size_t)(node0 + m) * 32 + kq];
        *(__half2*)&xs[m * XS1_STRIDE + kq * 4]     = __floats2half2_rn(v.x, v.y);
        *(__half2*)&xs[m * XS1_STRIDE + kq * 4 + 2] = __floats2half2_rn(v.z, v.w);
    }
#pragma unroll
    for (int i = 0; i < 8; i++) {
        int j = i * 256 + t;
        int n = j >> 4, q = j & 15;
        uint4 v = ((const uint4*)(g_w1t + (size_t)(ncol0 + n) * IND))[q];
        *(uint4*)&ws[n * WS1_STRIDE + q * 8] = v;
    }
    __syncthreads();
    int warp = t >> 5, lane = t & 31;
    int wm = warp & 1, wn = warp >> 1;
    int m_base = wm * 32, n_base = wn * 32;
    unsigned xs_sa = (unsigned)__cvta_generic_to_shared(xs);
    unsigned ws_sa = (unsigned)__cvta_generic_to_shared(ws);
    unsigned aA = xs_sa + ((m_base + ((lane >> 3) & 1) * 8 + (lane & 7)) * XS1_STRIDE
                           + (lane >> 4) * 8) * 2;
    unsigned aB = ws_sa + ((n_base + (lane >> 4) * 8 + (lane & 7)) * WS1_STRIDE
                           + ((lane >> 3) & 1) * 8) * 2;
    float c[2][4][4];
#pragma unroll
    for (int i = 0; i < 2; i++)
#pragma unroll
        for (int j = 0; j < 4; j++)
#pragma unroll
            for (int q = 0; q < 4; q++) c[i][j][q] = 0.f;
#pragma unroll
    for (int k0 = 0; k0 < IND; k0 += 16) {
        unsigned a0[4], a1[4], b0[4], b1[4];
        ldsm4(a0, aA + k0 * 2);
        ldsm4(a1, aA + (16 * XS1_STRIDE + k0) * 2);
        ldsm4(b0, aB + k0 * 2);
        ldsm4(b1, aB + (16 * WS1_STRIDE + k0) * 2);
        mma16816(c[0][0], a0, b0[0], b0[1]);
        mma16816(c[0][1], a0, b0[2], b0[3]);
        mma16816(c[0][2], a0, b1[0], b1[1]);
        mma16816(c[0][3], a0, b1[2], b1[3]);
        mma16816(c[1][0], a1, b0[0], b0[1]);
        mma16816(c[1][1], a1, b0[2], b0[3]);
        mma16816(c[1][2], a1, b1[0], b1[1]);
        mma16816(c[1][3], a1, b1[2], b1[3]);
    }
    int r = lane >> 2, kp = (lane & 3) * 2;
    __half* h1 = (__half*)g_h1h;
    // store h1 fp16
#pragma unroll
    for (int mt = 0; mt < 2; mt++) {
#pragma unroll
        for (int nt = 0; nt < 4; nt++) {
            int row = node0 + m_base + mt * 16 + r;
            int col = ncol0 + n_base + nt * 8 + kp;
            if (row < NN)
                *(__half2*)&h1[(size_t)row * C1 + col] =
                    __floats2half2_rn(c[mt][nt][0], c[mt][nt][1]);
            if (row + 8 < NN)
                *(__half2*)&h1[(size_t)(row + 8) * C1 + col] =
                    __floats2half2_rn(c[mt][nt][2], c[mt][nt][3]);
        }
    }
    // fused attention dots: partial over this warp's 32 cols, quad-reduce, REDG
    float ps[2][2] = {{0.f, 0.f}, {0.f, 0.f}};
    float pd[2][2] = {{0.f, 0.f}, {0.f, 0.f}};
#pragma unroll
    for (int nt = 0; nt < 4; nt++) {
        int colg = ncol0 + n_base + nt * 8 + kp;
        float sa0 = as1[colg], sa1 = as1[colg + 1];
        float da0 = ad1[colg], da1 = ad1[colg + 1];
#pragma unroll
        for (int mt = 0; mt < 2; mt++) {
            ps[mt][0] += c[mt][nt][0] * sa0 + c[mt][nt][1] * sa1;
            pd[mt][0] += c[mt][nt][0] * da0 + c[mt][nt][1] * da1;
            ps[mt][1] += c[mt][nt][2] * sa0 + c[mt][nt][3] * sa1;
            pd[mt][1] += c[mt][nt][2] * da0 + c[mt][nt][3] * da1;
        }
    }
#pragma unroll
    for (int o = 1; o <= 2; o <<= 1) {
#pragma unroll
        for (int mt = 0; mt < 2; mt++)
#pragma unroll
            for (int rh = 0; rh < 2; rh++) {
                ps[mt][rh] += __shfl_xor_sync(0xFFFFFFFFu, ps[mt][rh], o);
                pd[mt][rh] += __shfl_xor_sync(0xFFFFFFFFu, pd[mt][rh], o);
            }
    }
    if ((lane & 3) == 0) {
        int head = (ncol0 + n_base) >> 6;
        float* s1f = (float*)g_asrc1;
        float* d1f = (float*)g_adst1;
#pragma unroll
        for (int mt = 0; mt < 2; mt++)
#pragma unroll
            for (int rh = 0; rh < 2; rh++) {
                int row = node0 + m_base + mt * 16 + rh * 8 + r;
                if (row < NN) {
                    atomicAdd(&s1f[row * 4 + head], ps[mt][rh]);
                    atomicAdd(&d1f[row * 4 + head], pd[mt][rh]);
                }
            }
    }
}

// per-edge logits + CSR scatter fused
__global__ __launch_bounds__(256) void k_edge1(const int* __restrict__ ei,
                                               const float* __restrict__ eattr) {
    __shared__ float v1s[EDIM * HEADS];
    __shared__ float v2s[EDIM];
    if (threadIdx.x < EDIM * HEADS) v1s[threadIdx.x] = g_v1[threadIdx.x];
    if (threadIdx.x < EDIM)         v2s[threadIdx.x] = g_v2[threadIdx.x];
    __syncthreads();
    int e = blockIdx.x * blockDim.x + threadIdx.x;
    if (e >= NE) return;
    int s = ei[e], d = ei[NE + e];
    const float4* ea = (const float4*)(eattr + (size_t)e * EDIM);
    float ae[4] = {0.f, 0.f, 0.f, 0.f};
    float aev2 = 0.f;
#pragma unroll
    for (int j = 0; j < 4; j++) {
        float4 v = ea[j];
        float vals[4] = {v.x, v.y, v.z, v.w};
#pragma unroll
        for (int m = 0; m < 4; m++) {
            int dd = j * 4 + m;
            float ev = vals[m];
#pragma unroll
            for (int h = 0; h < 4; h++) ae[h] = fmaf(ev, v1s[dd * 4 + h], ae[h]);
            aev2 = fmaf(ev, v2s[dd], aev2);
        }
    }
    float4 av = g_asrc1[s], dv = g_adst1[d];
    float4 ex;
    ex.x = __expf(lrelu(av.x + dv.x + ae[0]));
    ex.y = __expf(lrelu(av.y + dv.y + ae[1]));
    ex.z = __expf(lrelu(av.z + dv.z + ae[2]));
    ex.w = __expf(lrelu(av.w + dv.w + ae[3]));
    unsigned pos = atomicAdd(&g_cnt[d], 1u);
    g_scr1[pos] = ex;
    g_misc[pos] = make_int2(s, __float_as_int(aev2));
}

// layer-1 aggregation: warp per dst node, 4-wide unroll; bias+relu epilogue
__global__ __launch_bounds__(256) void k_agg1(const float* __restrict__ b1) {
    int w = (blockIdx.x * blockDim.x + threadIdx.x) >> 5;
    int lane = threadIdx.x & 31;
    if (w >= NN) return;
    unsigned beg = g_ptr[w], end = g_ptr[w + 1];
    int h = lane >> 3;
    const float* scr = (const float*)g_scr1;
    float a[8] = {0.f, 0.f, 0.f, 0.f, 0.f, 0.f, 0.f, 0.f};
    float ds = 0.f;
    unsigned j = beg;
    for (; j + 4 <= end; j += 4) {
        int s0 = g_misc[j].x, s1 = g_misc[j + 1].x;
        int s2 = g_misc[j + 2].x, s3 = g_misc[j + 3].x;
        float x0 = scr[(size_t)j * 4 + h];
        float x1 = scr[(size_t)(j + 1) * 4 + h];
        float x2 = scr[(size_t)(j + 2) * 4 + h];
        float x3 = scr[(size_t)(j + 3) * 4 + h];
        uint4 v0 = g_h1h[(size_t)s0 * 32 + lane];
        uint4 v1 = g_h1h[(size_t)s1 * 32 + lane];
        uint4 v2 = g_h1h[(size_t)s2 * 32 + lane];
        uint4 v3 = g_h1h[(size_t)s3 * 32 + lane];
        ds += (x0 + x1) + (x2 + x3);
        float2 f;
        f = h2f(v0.x); a[0] = fmaf(f.x, x0, a[0]); a[1] = fmaf(f.y, x0, a[1]);
        f = h2f(v0.y); a[2] = fmaf(f.x, x0, a[2]); a[3] = fmaf(f.y, x0, a[3]);
        f = h2f(v0.z); a[4] = fmaf(f.x, x0, a[4]); a[5] = fmaf(f.y, x0, a[5]);
        f = h2f(v0.w); a[6] = fmaf(f.x, x0, a[6]); a[7] = fmaf(f.y, x0, a[7]);
        f = h2f(v1.x); a[0] = fmaf(f.x, x1, a[0]); a[1] = fmaf(f.y, x1, a[1]);
        f = h2f(v1.y); a[2] = fmaf(f.x, x1, a[2]); a[3] = fmaf(f.y, x1, a[3]);
        f = h2f(v1.z); a[4] = fmaf(f.x, x1, a[4]); a[5] = fmaf(f.y, x1, a[5]);
        f = h2f(v1.w); a[6] = fmaf(f.x, x1, a[6]); a[7] = fmaf(f.y, x1, a[7]);
        f = h2f(v2.x); a[0] = fmaf(f.x, x2, a[0]); a[1] = fmaf(f.y, x2, a[1]);
        f = h2f(v2.y); a[2] = fmaf(f.x, x2, a[2]); a[3] = fmaf(f.y, x2, a[3]);
        f = h2f(v2.z); a[4] = fmaf(f.x, x2, a[4]); a[5] = fmaf(f.y, x2, a[5]);
        f = h2f(v2.w); a[6] = fmaf(f.x, x2, a[6]); a[7] = fmaf(f.y, x2, a[7]);
        f = h2f(v3.x); a[0] = fmaf(f.x, x3, a[0]); a[1] = fmaf(f.y, x3, a[1]);
        f = h2f(v3.y); a[2] = fmaf(f.x, x3, a[2]); a[3] = fmaf(f.y, x3, a[3]);
        f = h2f(v3.z); a[4] = fmaf(f.x, x3, a[4]); a[5] = fmaf(f.y, x3, a[5]);
        f = h2f(v3.w); a[6] = fmaf(f.x, x3, a[6]); a[7] = fmaf(f.y, x3, a[7]);
    }
    for (; j < end; j++) {
        int s0 = g_misc[j].x;
        float x0 = scr[(size_t)j * 4 + h];
        uint4 v0 = g_h1h[(size_t)s0 * 32 + lane];
        ds += x0;
        float2 f;
        f = h2f(v0.x); a[0] = fmaf(f.x, x0, a[0]); a[1] = fmaf(f.y, x0, a[1]);
        f = h2f(v0.y); a[2] = fmaf(f.x, x0, a[2]); a[3] = fmaf(f.y, x0, a[3]);
        f = h2f(v0.z); a[4] = fmaf(f.x, x0, a[4]); a[5] = fmaf(f.y, x0, a[5]);
        f = h2f(v0.w); a[6] = fmaf(f.x, x0, a[6]); a[7] = fmaf(f.y, x0, a[7]);
    }
    float inv = 1.f / (ds + 1e-16f);
    float4 b0 = ((const float4*)b1)[2 * lane];
    float4 b1v = ((const float4*)b1)[2 * lane + 1];
    __half2 r0 = __floats2half2_rn(fmaxf(a[0] * inv + b0.x, 0.f),
                                   fmaxf(a[1] * inv + b0.y, 0.f));
    __half2 r1 = __floats2half2_rn(fmaxf(a[2] * inv + b0.z, 0.f),
                                   fmaxf(a[3] * inv + b0.w, 0.f));
    __half2 r2 = __floats2half2_rn(fmaxf(a[4] * inv + b1v.x, 0.f),
                                   fmaxf(a[5] * inv + b1v.y, 0.f));
    __half2 r3 = __floats2half2_rn(fmaxf(a[6] * inv + b1v.z, 0.f),
                                   fmaxf(a[7] * inv + b1v.w, 0.f));
    uint4 pk;
    pk.x = *(unsigned*)&r0; pk.y = *(unsigned*)&r1;
    pk.z = *(unsigned*)&r2; pk.w = *(unsigned*)&r3;
    *reinterpret_cast<uint4*>(&g_out1h[(size_t)w * 128 + lane * 4]) = pk;
}

// ---- h2 = out1 @ W2 via HMMA+LDSM, att2 dots fused in epilogue ----
#define XS2_STRIDE 264
#define WS2_STRIDE 264
#define G2_SMEM ((64 * XS2_STRIDE + 64 * WS2_STRIDE) * 2)

__global__ __launch_bounds__(256) void k_gemm2(const float* __restrict__ as2,
                                               const float* __restrict__ ad2) {
    extern __shared__ __half sm2[];
    __half* xs = sm2;                     // [64 m][264 k]
    __half* ws = sm2 + 64 * XS2_STRIDE;   // [64 n][264 k]
    int t = threadIdx.x;
    int node0 = blockIdx.x * 64;
#pragma unroll
    for (int i = 0; i < 8; i++) {
        int j = i * 256 + t;
        int m = j >> 5, q = j & 31;
        uint4 v = make_uint4(0u, 0u, 0u, 0u);
        if (node0 + m < NN)
            v = ((const uint4*)g_out1h)[(size_t)(node0 + m) * 32 + q];
        *(uint4*)&xs[m * XS2_STRIDE + q * 8] = v;
    }
#pragma unroll
    for (int i = 0; i < 8; i++) {
        int j = i * 256 + t;
        int n = j >> 5, q = j & 31;
        uint4 v = ((const uint4*)(g_w2t + (size_t)n * C1))[q];
        *(uint4*)&ws[n * WS2_STRIDE + q * 8] = v;
    }
    __syncthreads();
    int warp = t >> 5, lane = t & 31;
    int wm = warp & 3, wn = warp >> 2;
    int m_base = wm * 16, n_base = wn * 32;
    unsigned xs_sa = (unsigned)__cvta_generic_to_shared(xs);
    unsigned ws_sa = (unsigned)__cvta_generic_to_shared(ws);
    unsigned aA = xs_sa + ((m_base + ((lane >> 3) & 1) * 8 + (lane & 7)) * XS2_STRIDE
                           + (lane >> 4) * 8) * 2;
    unsigned aB = ws_sa + ((n_base + (lane >> 4) * 8 + (lane & 7)) * WS2_STRIDE
                           + ((lane >> 3) & 1) * 8) * 2;
    float c[4][4];
#pragma unroll
    for (int j = 0; j < 4; j++)
#pragma unroll
        for (int q = 0; q < 4; q++) c[j][q] = 0.f;
#pragma unroll
    for (int k0 = 0; k0 < C1; k0 += 16) {
        unsigned a[4], b0[4], b1[4];
        ldsm4(a, aA + k0 * 2);
        ldsm4(b0, aB + k0 * 2);
        ldsm4(b1, aB + (16 * WS2_STRIDE + k0) * 2);
        mma16816(c[0], a, b0[0], b0[1]);
        mma16816(c[1], a, b0[2], b0[3]);
        mma16816(c[2], a, b1[0], b1[1]);
        mma16816(c[3], a, b1[2], b1[3]);
    }
    int r = lane >> 2, kp = (lane & 3) * 2;
    __half* h2 = (__half*)g_h2h;
#pragma unroll
    for (int nt = 0; nt < 4; nt++) {
        int row = node0 + m_base + r;
        int col = n_base + nt * 8 + kp;
        if (row < NN)
            *(__half2*)&h2[(size_t)row * HID + col] =
                __floats2half2_rn(c[nt][0], c[nt][1]);
        if (row + 8 < NN)
            *(__half2*)&h2[(size_t)(row + 8) * HID + col] =
                __floats2half2_rn(c[nt][2], c[nt][3]);
    }
    // fused layer-2 attention dots
    float ps[2] = {0.f, 0.f}, pd[2] = {0.f, 0.f};
#pragma unroll
    for (int nt = 0; nt < 4; nt++) {
        int colg = n_base + nt * 8 + kp;
        float sa0 = as2[colg], sa1 = as2[colg + 1];
        float da0 = ad2[colg], da1 = ad2[colg + 1];
        ps[0] += c[nt][0] * sa0 + c[nt][1] * sa1;
        pd[0] += c[nt][0] * da0 + c[nt][1] * da1;
        ps[1] += c[nt][2] * sa0 + c[nt][3] * sa1;
        pd[1] += c[nt][2] * da0 + c[nt][3] * da1;
    }
#pragma unroll
    for (int o = 1; o <= 2; o <<= 1) {
#pragma unroll
        for (int rh = 0; rh < 2; rh++) {
            ps[rh] += __shfl_xor_sync(0xFFFFFFFFu, ps[rh], o);
            pd[rh] += __shfl_xor_sync(0xFFFFFFFFu, pd[rh], o);
        }
    }
    if ((lane & 3) == 0) {
#pragma unroll
        for (int rh = 0; rh < 2; rh++) {
            int row = node0 + m_base + rh * 8 + r;
            if (row < NN) {
                atomicAdd(&g_asrc2[row], ps[rh]);
                atomicAdd(&g_adst2[row], pd[rh]);
            }
        }
    }
}

// layer-2 aggregation + final linear: warp per dst node, 4-wide unroll
__global__ __launch_bounds__(256) void k_agg2(const float* __restrict__ b2,
                                              const float* __restrict__ Wlin,
                                              const float* __restrict__ blin,
                                              float* __restrict__ out) {
    int w = (blockIdx.x * blockDim.x + threadIdx.x) >> 5;
    int lane = threadIdx.x & 31;
    if (w >= NN) return;
    unsigned beg = g_ptr[w], end = g_ptr[w + 1];
    float adw = g_adst2[w];
    float2 acc = make_float2(0.f, 0.f);
    float ds = 0.f;
    unsigned j = beg;
    for (; j + 4 <= end; j += 4) {
        int2 m0 = g_misc[j], m1 = g_misc[j + 1];
        int2 m2 = g_misc[j + 2], m3 = g_misc[j + 3];
        float a0 = g_asrc2[m0.x], a1 = g_asrc2[m1.x];
        float a2 = g_asrc2[m2.x], a3 = g_asrc2[m3.x];
        __half2 v0 = g_h2h[(size_t)m0.x * 32 + lane];
        __half2 v1 = g_h2h[(size_t)m1.x * 32 + lane];
        __half2 v2 = g_h2h[(size_t)m2.x * 32 + lane];
        __half2 v3 = g_h2h[(size_t)m3.x * 32 + lane];
        float al0 = __expf(lrelu(a0 + adw + __int_as_float(m0.y)));
        float al1 = __expf(lrelu(a1 + adw + __int_as_float(m1.y)));
        float al2 = __expf(lrelu(a2 + adw + __int_as_float(m2.y)));
        float al3 = __expf(lrelu(a3 + adw + __int_as_float(m3.y)));
        ds += (al0 + al1) + (al2 + al3);
        float2 f;
        f = __half22float2(v0); acc.x = fmaf(f.x, al0, acc.x); acc.y = fmaf(f.y, al0, acc.y);
        f = __half22float2(v1); acc.x = fmaf(f.x, al1, acc.x); acc.y = fmaf(f.y, al1, acc.y);
        f = __half22float2(v2); acc.x = fmaf(f.x, al2, acc.x); acc.y = fmaf(f.y, al2, acc.y);
        f = __half22float2(v3); acc.x = fmaf(f.x, al3, acc.x); acc.y = fmaf(f.y, al3, acc.y);
    }
    for (; j < end; j++) {
        int2 m0 = g_misc[j];
        float al0 = __expf(lrelu(g_asrc2[m0.x] + adw + __int_as_float(m0.y)));
        ds += al0;
        float2 f = __half22float2(g_h2h[(size_t)m0.x * 32 + lane]);
        acc.x = fmaf(f.x, al0, acc.x); acc.y = fmaf(f.y, al0, acc.y);
    }
    float inv = 1.f / (ds + 1e-16f);
    float v0 = fmaxf(acc.x * inv + b2[2 * lane], 0.f);
    float v1 = fmaxf(acc.y * inv + b2[2 * lane + 1], 0.f);
    float r = v0 * Wlin[2 * lane] + v1 * Wlin[2 * lane + 1];
#pragma unroll
    for (int o = 16; o >= 1; o >>= 1) r += __shfl_xor_sync(0xFFFFFFFFu, r, o);
    if (lane == 0) out[w] = r + blin[0];
}

// ---------------- launch ----------------
extern "C" void kernel_launch(void* const* d_in, const int* in_sizes, int n_in,
                              void* d_out, int out_size) {
    const float* x     = (const float*)d_in[0];
    const int*   ei    = (const int*)d_in[1];
    const float* eattr = (const float*)d_in[2];
    const float* W1    = (const float*)d_in[3];
    const float* We1   = (const float*)d_in[4];
    const float* as1   = (const float*)d_in[5];
    const float* ad1   = (const float*)d_in[6];
    const float* ae1   = (const float*)d_in[7];
    const float* b1    = (const float*)d_in[8];
    const float* W2    = (const float*)d_in[9];
    const float* We2   = (const float*)d_in[10];
    const float* as2   = (const float*)d_in[11];
    const float* ad2   = (const float*)d_in[12];
    const float* ae2   = (const float*)d_in[13];
    const float* b2    = (const float*)d_in[14];
    const float* Wlin  = (const float*)d_in[15];
    const float* blin  = (const float*)d_in[16];
    float* out = (float*)d_out;

    static bool attr_done = false;
    if (!attr_done) {
        cudaFuncSetAttribute(k_gemm1, cudaFuncAttributeMaxDynamicSharedMemorySize, G1_SMEM);
        cudaFuncSetAttribute(k_gemm2, cudaFuncAttributeMaxDynamicSharedMemorySize, G2_SMEM);
        attr_done = true;
    }

    k_init<<<(NN + 255) / 256, 256>>>(We1, ae1, We2, ae2, W1, W2);
    k_hist<<<NE / 256, 256>>>(ei);
    k_scan<<<1, 1024>>>();
    k_gemm1<<<dim3((NN + 63) / 64, 2), 256, G1_SMEM>>>(x, as1, ad1);
    k_edge1<<<NE / 256, 256>>>(ei, eattr);
    k_agg1<<<(NN * 32 + 255) / 256, 256>>>(b1);
    k_gemm2<<<(NN + 63) / 64, 256, G2_SMEM>>>(as2, ad2);
    k_agg2<<<(NN * 32 + 255) / 256, 256>>>(b2, Wlin, blin, out);
}

// round 11
// speedup vs baseline: 2.1715x; 1.1460x over previous
#include <cuda_runtime.h>
#include <cuda_fp16.h>

#define NN 50000
#define NE 800000
#define IND 128
#define HID 64
#define HEADS 4
#define C1 256            // HEADS*HID
#define EDIM 16

// ---------------- scratch (device globals) ----------------
__device__ uint4    g_h1h[NN * 32];         // [N,256] h1, fp16
__device__ __half2  g_out1h[NN * 128];      // [N,256] relu(agg1+b1), fp16
__device__ __half2  g_h2h[NN * 32];         // [N,64]  h2, fp16
__device__ __half   g_w1t[C1 * IND];        // W1^T fp16 [256 n][128 k]
__device__ __half   g_w2t[HID * C1];        // W2^T fp16 [64 n][256 k]
__device__ float4   g_scr1[NE];             // exp(logits) 4 heads, AT CSR POS
__device__ int2     g_misc[NE];             // (src, ae2-bits), AT CSR POS
__device__ float4   g_asrc1[NN], g_adst1[NN];
__device__ float    g_asrc2[NN], g_adst2[NN];
__device__ float    g_v1[EDIM * HEADS];
__device__ float    g_v2[EDIM];
__device__ unsigned g_deg[NN];
__device__ unsigned g_cnt[NN];
__device__ unsigned g_ptr[NN + 1];

// ---------------- helpers ----------------
__device__ __forceinline__ float lrelu(float x) { return x > 0.f ? x : 0.2f * x; }
__device__ __forceinline__ float2 h2f(unsigned u) {
    return __half22float2(*reinterpret_cast<__half2*>(&u));
}
__device__ __forceinline__ void mma16816(float* c, const unsigned* a,
                                         unsigned b0, unsigned b1) {
    asm volatile(
        "mma.sync.aligned.m16n8k16.row.col.f32.f16.f16.f32 "
        "{%0,%1,%2,%3}, {%4,%5,%6,%7}, {%8,%9}, {%0,%1,%2,%3};"
        : "+f"(c[0]), "+f"(c[1]), "+f"(c[2]), "+f"(c[3])
        : "r"(a[0]), "r"(a[1]), "r"(a[2]), "r"(a[3]), "r"(b0), "r"(b1));
}
__device__ __forceinline__ void ldsm4(unsigned* r, unsigned addr) {
    asm volatile("ldmatrix.sync.aligned.m8n8.x4.shared.b16 {%0,%1,%2,%3}, [%4];"
                 : "=r"(r[0]), "=r"(r[1]), "=r"(r[2]), "=r"(r[3]) : "r"(addr));
}

// ---------------- kernels ----------------
// stream B: zero degree counters
__global__ __launch_bounds__(256) void k_initdeg() {
    int i = blockIdx.x * blockDim.x + threadIdx.x;
    if (i < NN) g_deg[i] = 0u;
}

// stream A: weights transpose + zero attention accumulators + edge vecs
__global__ __launch_bounds__(256) void k_initw(const float* __restrict__ We1,
                                               const float* __restrict__ ae1,
                                               const float* __restrict__ We2,
                                               const float* __restrict__ ae2,
                                               const float* __restrict__ W1,
                                               const float* __restrict__ W2) {
    int i = blockIdx.x * blockDim.x + threadIdx.x;
    if (i < NN) {
        float4 z = make_float4(0.f, 0.f, 0.f, 0.f);
        g_asrc1[i] = z; g_adst1[i] = z;
        g_asrc2[i] = 0.f; g_adst2[i] = 0.f;
    }
    if (i < C1 * IND) {
        int n = i >> 7, k = i & 127;
        g_w1t[i] = __float2half_rn(W1[k * C1 + n]);
    }
    if (i < HID * C1) {
        int n = i >> 8, k = i & 255;
        g_w2t[i] = __float2half_rn(W2[k * HID + n]);
    }
    if (blockIdx.x == 0) {
        int t = threadIdx.x;
        if (t < EDIM * HEADS) {
            int d = t >> 2, h = t & 3;
            float s = 0.f;
            for (int c = 0; c < HID; c++) s += We1[d * C1 + h * HID + c] * ae1[h * HID + c];
            g_v1[t] = s;
        }
        if (t < EDIM) {
            float s = 0.f;
            for (int c = 0; c < HID; c++) s += We2[t * HID + c] * ae2[c];
            g_v2[t] = s;
        }
    }
}

__global__ __launch_bounds__(256) void k_hist(const int* __restrict__ ei) {
    int e = blockIdx.x * blockDim.x + threadIdx.x;
    if (e < NE) atomicAdd(&g_deg[ei[NE + e]], 1u);
}

// single-block exclusive scan of degrees -> g_ptr, g_cnt
__global__ __launch_bounds__(1024) void k_scan() {
    __shared__ unsigned wsum[32];
    const int T = 1024;
    int t = threadIdx.x;
    int per = (NN + T - 1) / T;
    int b = t * per, e = min(b + per, NN);
    unsigned s = 0;
    for (int i = b; i < e; i++) s += g_deg[i];
    unsigned lane = t & 31, wid = t >> 5;
    unsigned incl = s;
#pragma unroll
    for (int o = 1; o < 32; o <<= 1) {
        unsigned u = __shfl_up_sync(0xFFFFFFFFu, incl, o);
        if (lane >= (unsigned)o) incl += u;
    }
    if (lane == 31) wsum[wid] = incl;
    __syncthreads();
    if (wid == 0) {
        unsigned v = wsum[lane];
        unsigned vi = v;
#pragma unroll
        for (int o = 1; o < 32; o <<= 1) {
            unsigned u = __shfl_up_sync(0xFFFFFFFFu, vi, o);
            if (lane >= (unsigned)o) vi += u;
        }
        wsum[lane] = vi - v;
    }
    __syncthreads();
    unsigned run = incl - s + wsum[wid];
    for (int i = b; i < e; i++) {
        unsigned d = g_deg[i];
        g_ptr[i] = run;
        g_cnt[i] = run;
        run += d;
    }
    if (t == T - 1) g_ptr[NN] = NE;
}

// ---- h1 = x @ W1 via HMMA+LDSM, att1 dots fused in epilogue ----
#define XS1_STRIDE 136
#define WS1_STRIDE 136
#define G1_SMEM ((64 * XS1_STRIDE + 128 * WS1_STRIDE) * 2)

__global__ __launch_bounds__(256) void k_gemm1(const float* __restrict__ x,
                                               const float* __restrict__ as1,
                                               const float* __restrict__ ad1) {
    extern __shared__ __half sm1[];
    __half* xs = sm1;                     // [64 m][136 k]
    __half* ws = sm1 + 64 * XS1_STRIDE;   // [128 n][136 k]
    int t = threadIdx.x;
    int node0 = blockIdx.x * 64;
    int ncol0 = blockIdx.y * 128;
#pragma unroll
    for (int i = 0; i < 8; i++) {
        int j = i * 256 + t;
        int m = j >> 5, kq = j & 31;
        float4 v = make_float4(0.f, 0.f, 0.f, 0.f);
        if (node0 + m < NN) v = ((const float4*)x)[(size_t)(node0 + m) * 32 + kq];
        *(__half2*)&xs[m * XS1_STRIDE + kq * 4]     = __floats2half2_rn(v.x, v.y);
        *(__half2*)&xs[m * XS1_STRIDE + kq * 4 + 2] = __floats2half2_rn(v.z, v.w);
    }
#pragma unroll
    for (int i = 0; i < 8; i++) {
        int j = i * 256 + t;
        int n = j >> 4, q = j & 15;
        uint4 v = ((const uint4*)(g_w1t + (size_t)(ncol0 + n) * IND))[q];
        *(uint4*)&ws[n * WS1_STRIDE + q * 8] = v;
    }
    __syncthreads();
    int warp = t >> 5, lane = t & 31;
    int wm = warp & 1, wn = warp >> 1;
    int m_base = wm * 32, n_base = wn * 32;
    unsigned xs_sa = (unsigned)__cvta_generic_to_shared(xs);
    unsigned ws_sa = (unsigned)__cvta_generic_to_shared(ws);
    unsigned aA = xs_sa + ((m_base + ((lane >> 3) & 1) * 8 + (lane & 7)) * XS1_STRIDE
                           + (lane >> 4) * 8) * 2;
    unsigned aB = ws_sa + ((n_base + (lane >> 4) * 8 + (lane & 7)) * WS1_STRIDE
                           + ((lane >> 3) & 1) * 8) * 2;
    float c[2][4][4];
#pragma unroll
    for (int i = 0; i < 2; i++)
#pragma unroll
        for (int j = 0; j < 4; j++)
#pragma unroll
            for (int q = 0; q < 4; q++) c[i][j][q] = 0.f;
#pragma unroll
    for (int k0 = 0; k0 < IND; k0 += 16) {
        unsigned a0[4], a1[4], b0[4], b1[4];
        ldsm4(a0, aA + k0 * 2);
        ldsm4(a1, aA + (16 * XS1_STRIDE + k0) * 2);
        ldsm4(b0, aB + k0 * 2);
        ldsm4(b1, aB + (16 * WS1_STRIDE + k0) * 2);
        mma16816(c[0][0], a0, b0[0], b0[1]);
        mma16816(c[0][1], a0, b0[2], b0[3]);
        mma16816(c[0][2], a0, b1[0], b1[1]);
        mma16816(c[0][3], a0, b1[2], b1[3]);
        mma16816(c[1][0], a1, b0[0], b0[1]);
        mma16816(c[1][1], a1, b0[2], b0[3]);
        mma16816(c[1][2], a1, b1[0], b1[1]);
        mma16816(c[1][3], a1, b1[2], b1[3]);
    }
    int r = lane >> 2, kp = (lane & 3) * 2;
    __half* h1 = (__half*)g_h1h;
#pragma unroll
    for (int mt = 0; mt < 2; mt++) {
#pragma unroll
        for (int nt = 0; nt < 4; nt++) {
            int row = node0 + m_base + mt * 16 + r;
            int col = ncol0 + n_base + nt * 8 + kp;
            if (row < NN)
                *(__half2*)&h1[(size_t)row * C1 + col] =
                    __floats2half2_rn(c[mt][nt][0], c[mt][nt][1]);
            if (row + 8 < NN)
                *(__half2*)&h1[(size_t)(row + 8) * C1 + col] =
                    __floats2half2_rn(c[mt][nt][2], c[mt][nt][3]);
        }
    }
    // fused attention dots: partial over this warp's 32 cols, quad-reduce, REDG
    float ps[2][2] = {{0.f, 0.f}, {0.f, 0.f}};
    float pd[2][2] = {{0.f, 0.f}, {0.f, 0.f}};
#pragma unroll
    for (int nt = 0; nt < 4; nt++) {
        int colg = ncol0 + n_base + nt * 8 + kp;
        float sa0 = as1[colg], sa1 = as1[colg + 1];
        float da0 = ad1[colg], da1 = ad1[colg + 1];
#pragma unroll
        for (int mt = 0; mt < 2; mt++) {
            ps[mt][0] += c[mt][nt][0] * sa0 + c[mt][nt][1] * sa1;
            pd[mt][0] += c[mt][nt][0] * da0 + c[mt][nt][1] * da1;
            ps[mt][1] += c[mt][nt][2] * sa0 + c[mt][nt][3] * sa1;
            pd[mt][1] += c[mt][nt][2] * da0 + c[mt][nt][3] * da1;
        }
    }
#pragma unroll
    for (int o = 1; o <= 2; o <<= 1) {
#pragma unroll
        for (int mt = 0; mt < 2; mt++)
#pragma unroll
            for (int rh = 0; rh < 2; rh++) {
                ps[mt][rh] += __shfl_xor_sync(0xFFFFFFFFu, ps[mt][rh], o);
                pd[mt][rh] += __shfl_xor_sync(0xFFFFFFFFu, pd[mt][rh], o);
            }
    }
    if ((lane & 3) == 0) {
        int head = (ncol0 + n_base) >> 6;
        float* s1f = (float*)g_asrc1;
        float* d1f = (float*)g_adst1;
#pragma unroll
        for (int mt = 0; mt < 2; mt++)
#pragma unroll
            for (int rh = 0; rh < 2; rh++) {
                int row = node0 + m_base + mt * 16 + rh * 8 + r;
                if (row < NN) {
                    atomicAdd(&s1f[row * 4 + head], ps[mt][rh]);
                    atomicAdd(&d1f[row * 4 + head], pd[mt][rh]);
                }
            }
    }
}

// per-edge logits + CSR scatter fused; 2 edges/thread for MLP
__global__ __launch_bounds__(256) void k_edge1(const int* __restrict__ ei,
                                               const float* __restrict__ eattr) {
    __shared__ float v1s[EDIM * HEADS];
    __shared__ float v2s[EDIM];
    if (threadIdx.x < EDIM * HEADS) v1s[threadIdx.x] = g_v1[threadIdx.x];
    if (threadIdx.x < EDIM)         v2s[threadIdx.x] = g_v2[threadIdx.x];
    __syncthreads();
    int base = blockIdx.x * blockDim.x + threadIdx.x;
    if (base >= NE / 2) return;
    int eidx[2] = {base, base + NE / 2};
    int s[2], d[2];
    float4 av[2], dv[2];
#pragma unroll
    for (int u = 0; u < 2; u++) {
        s[u] = ei[eidx[u]];
        d[u] = ei[NE + eidx[u]];
    }
#pragma unroll
    for (int u = 0; u < 2; u++) {
        av[u] = g_asrc1[s[u]];
        dv[u] = g_adst1[d[u]];
    }
#pragma unroll
    for (int u = 0; u < 2; u++) {
        const float4* ea = (const float4*)(eattr + (size_t)eidx[u] * EDIM);
        float ae[4] = {0.f, 0.f, 0.f, 0.f};
        float aev2 = 0.f;
#pragma unroll
        for (int j = 0; j < 4; j++) {
            float4 v = ea[j];
            float vals[4] = {v.x, v.y, v.z, v.w};
#pragma unroll
            for (int m = 0; m < 4; m++) {
                int dd = j * 4 + m;
                float ev = vals[m];
#pragma unroll
                for (int h = 0; h < 4; h++) ae[h] = fmaf(ev, v1s[dd * 4 + h], ae[h]);
                aev2 = fmaf(ev, v2s[dd], aev2);
            }
        }
        float4 ex;
        ex.x = __expf(lrelu(av[u].x + dv[u].x + ae[0]));
        ex.y = __expf(lrelu(av[u].y + dv[u].y + ae[1]));
        ex.z = __expf(lrelu(av[u].z + dv[u].z + ae[2]));
        ex.w = __expf(lrelu(av[u].w + dv[u].w + ae[3]));
        unsigned pos = atomicAdd(&g_cnt[d[u]], 1u);
        g_scr1[pos] = ex;
        g_misc[pos] = make_int2(s[u], __float_as_int(aev2));
    }
}

// layer-1 aggregation: warp per dst node, 4-wide unroll; bias+relu epilogue
__global__ __launch_bounds__(256) void k_agg1(const float* __restrict__ b1) {
    int w = (blockIdx.x * blockDim.x + threadIdx.x) >> 5;
    int lane = threadIdx.x & 31;
    if (w >= NN) return;
    unsigned beg = g_ptr[w], end = g_ptr[w + 1];
    int h = lane >> 3;
    const float* scr = (const float*)g_scr1;
    float a[8] = {0.f, 0.f, 0.f, 0.f, 0.f, 0.f, 0.f, 0.f};
    float ds = 0.f;
    unsigned j = beg;
    for (; j + 4 <= end; j += 4) {
        int s0 = g_misc[j].x, s1 = g_misc[j + 1].x;
        int s2 = g_misc[j + 2].x, s3 = g_misc[j + 3].x;
        float x0 = scr[(size_t)j * 4 + h];
        float x1 = scr[(size_t)(j + 1) * 4 + h];
        float x2 = scr[(size_t)(j + 2) * 4 + h];
        float x3 = scr[(size_t)(j + 3) * 4 + h];
        uint4 v0 = g_h1h[(size_t)s0 * 32 + lane];
        uint4 v1 = g_h1h[(size_t)s1 * 32 + lane];
        uint4 v2 = g_h1h[(size_t)s2 * 32 + lane];
        uint4 v3 = g_h1h[(size_t)s3 * 32 + lane];
        ds += (x0 + x1) + (x2 + x3);
        float2 f;
        f = h2f(v0.x); a[0] = fmaf(f.x, x0, a[0]); a[1] = fmaf(f.y, x0, a[1]);
        f = h2f(v0.y); a[2] = fmaf(f.x, x0, a[2]); a[3] = fmaf(f.y, x0, a[3]);
        f = h2f(v0.z); a[4] = fmaf(f.x, x0, a[4]); a[5] = fmaf(f.y, x0, a[5]);
        f = h2f(v0.w); a[6] = fmaf(f.x, x0, a[6]); a[7] = fmaf(f.y, x0, a[7]);
        f = h2f(v1.x); a[0] = fmaf(f.x, x1, a[0]); a[1] = fmaf(f.y, x1, a[1]);
        f = h2f(v1.y); a[2] = fmaf(f.x, x1, a[2]); a[3] = fmaf(f.y, x1, a[3]);
        f = h2f(v1.z); a[4] = fmaf(f.x, x1, a[4]); a[5] = fmaf(f.y, x1, a[5]);
        f = h2f(v1.w); a[6] = fmaf(f.x, x1, a[6]); a[7] = fmaf(f.y, x1, a[7]);
        f = h2f(v2.x); a[0] = fmaf(f.x, x2, a[0]); a[1] = fmaf(f.y, x2, a[1]);
        f = h2f(v2.y); a[2] = fmaf(f.x, x2, a[2]); a[3] = fmaf(f.y, x2, a[3]);
        f = h2f(v2.z); a[4] = fmaf(f.x, x2, a[4]); a[5] = fmaf(f.y, x2, a[5]);
        f = h2f(v2.w); a[6] = fmaf(f.x, x2, a[6]); a[7] = fmaf(f.y, x2, a[7]);
        f = h2f(v3.x); a[0] = fmaf(f.x, x3, a[0]); a[1] = fmaf(f.y, x3, a[1]);
        f = h2f(v3.y); a[2] = fmaf(f.x, x3, a[2]); a[3] = fmaf(f.y, x3, a[3]);
        f = h2f(v3.z); a[4] = fmaf(f.x, x3, a[4]); a[5] = fmaf(f.y, x3, a[5]);
        f = h2f(v3.w); a[6] = fmaf(f.x, x3, a[6]); a[7] = fmaf(f.y, x3, a[7]);
    }
    for (; j < end; j++) {
        int s0 = g_misc[j].x;
        float x0 = scr[(size_t)j * 4 + h];
        uint4 v0 = g_h1h[(size_t)s0 * 32 + lane];
        ds += x0;
        float2 f;
        f = h2f(v0.x); a[0] = fmaf(f.x, x0, a[0]); a[1] = fmaf(f.y, x0, a[1]);
        f = h2f(v0.y); a[2] = fmaf(f.x, x0, a[2]); a[3] = fmaf(f.y, x0, a[3]);
        f = h2f(v0.z); a[4] = fmaf(f.x, x0, a[4]); a[5] = fmaf(f.y, x0, a[5]);
        f = h2f(v0.w); a[6] = fmaf(f.x, x0, a[6]); a[7] = fmaf(f.y, x0, a[7]);
    }
    float inv = 1.f / (ds + 1e-16f);
    float4 b0 = ((const float4*)b1)[2 * lane];
    float4 b1v = ((const float4*)b1)[2 * lane + 1];
    __half2 r0 = __floats2half2_rn(fmaxf(a[0] * inv + b0.x, 0.f),
                                   fmaxf(a[1] * inv + b0.y, 0.f));
    __half2 r1 = __floats2half2_rn(fmaxf(a[2] * inv + b0.z, 0.f),
                                   fmaxf(a[3] * inv + b0.w, 0.f));
    __half2 r2 = __floats2half2_rn(fmaxf(a[4] * inv + b1v.x, 0.f),
                                   fmaxf(a[5] * inv + b1v.y, 0.f));
    __half2 r3 = __floats2half2_rn(fmaxf(a[6] * inv + b1v.z, 0.f),
                                   fmaxf(a[7] * inv + b1v.w, 0.f));
    uint4 pk;
    pk.x = *(unsigned*)&r0; pk.y = *(unsigned*)&r1;
    pk.z = *(unsigned*)&r2; pk.w = *(unsigned*)&r3;
    *reinterpret_cast<uint4*>(&g_out1h[(size_t)w * 128 + lane * 4]) = pk;
}

// ---- h2 = out1 @ W2 via HMMA+LDSM, att2 dots fused in epilogue ----
#define XS2_STRIDE 264
#define WS2_STRIDE 264
#define G2_SMEM ((64 * XS2_STRIDE + 64 * WS2_STRIDE) * 2)

__global__ __launch_bounds__(256) void k_gemm2(const float* __restrict__ as2,
                                               const float* __restrict__ ad2) {
    extern __shared__ __half sm2[];
    __half* xs = sm2;                     // [64 m][264 k]
    __half* ws = sm2 + 64 * XS2_STRIDE;   // [64 n][264 k]
    int t = threadIdx.x;
    int node0 = blockIdx.x * 64;
#pragma unroll
    for (int i = 0; i < 8; i++) {
        int j = i * 256 + t;
        int m = j >> 5, q = j & 31;
        uint4 v = make_uint4(0u, 0u, 0u, 0u);
        if (node0 + m < NN)
            v = ((const uint4*)g_out1h)[(size_t)(node0 + m) * 32 + q];
        *(uint4*)&xs[m * XS2_STRIDE + q * 8] = v;
    }
#pragma unroll
    for (int i = 0; i < 8; i++) {
        int j = i * 256 + t;
        int n = j >> 5, q = j & 31;
        uint4 v = ((const uint4*)(g_w2t + (size_t)n * C1))[q];
        *(uint4*)&ws[n * WS2_STRIDE + q * 8] = v;
    }
    __syncthreads();
    int warp = t >> 5, lane = t & 31;
    int wm = warp & 3, wn = warp >> 2;
    int m_base = wm * 16, n_base = wn * 32;
    unsigned xs_sa = (unsigned)__cvta_generic_to_shared(xs);
    unsigned ws_sa = (unsigned)__cvta_generic_to_shared(ws);
    unsigned aA = xs_sa + ((m_base + ((lane >> 3) & 1) * 8 + (lane & 7)) * XS2_STRIDE
                           + (lane >> 4) * 8) * 2;
    unsigned aB = ws_sa + ((n_base + (lane >> 4) * 8 + (lane & 7)) * WS2_STRIDE
                           + ((lane >> 3) & 1) * 8) * 2;
    float c[4][4];
#pragma unroll
    for (int j = 0; j < 4; j++)
#pragma unroll
        for (int q = 0; q < 4; q++) c[j][q] = 0.f;
#pragma unroll
    for (int k0 = 0; k0 < C1; k0 += 16) {
        unsigned a[4], b0[4], b1[4];
        ldsm4(a, aA + k0 * 2);
        ldsm4(b0, aB + k0 * 2);
        ldsm4(b1, aB + (16 * WS2_STRIDE + k0) * 2);
        mma16816(c[0], a, b0[0], b0[1]);
        mma16816(c[1], a, b0[2], b0[3]);
        mma16816(c[2], a, b1[0], b1[1]);
        mma16816(c[3], a, b1[2], b1[3]);
    }
    int r = lane >> 2, kp = (lane & 3) * 2;
    __half* h2 = (__half*)g_h2h;
#pragma unroll
    for (int nt = 0; nt < 4; nt++) {
        int row = node0 + m_base + r;
        int col = n_base + nt * 8 + kp;
        if (row < NN)
            *(__half2*)&h2[(size_t)row * HID + col] =
                __floats2half2_rn(c[nt][0], c[nt][1]);
        if (row + 8 < NN)
            *(__half2*)&h2[(size_t)(row + 8) * HID + col] =
                __floats2half2_rn(c[nt][2], c[nt][3]);
    }
    float ps[2] = {0.f, 0.f}, pd[2] = {0.f, 0.f};
#pragma unroll
    for (int nt = 0; nt < 4; nt++) {
        int colg = n_base + nt * 8 + kp;
        float sa0 = as2[colg], sa1 = as2[colg + 1];
        float da0 = ad2[colg], da1 = ad2[colg + 1];
        ps[0] += c[nt][0] * sa0 + c[nt][1] * sa1;
        pd[0] += c[nt][0] * da0 + c[nt][1] * da1;
        ps[1] += c[nt][2] * sa0 + c[nt][3] * sa1;
        pd[1] += c[nt][2] * da0 + c[nt][3] * da1;
    }
#pragma unroll
    for (int o = 1; o <= 2; o <<= 1) {
#pragma unroll
        for (int rh = 0; rh < 2; rh++) {
            ps[rh] += __shfl_xor_sync(0xFFFFFFFFu, ps[rh], o);
            pd[rh] += __shfl_xor_sync(0xFFFFFFFFu, pd[rh], o);
        }
    }
    if ((lane & 3) == 0) {
#pragma unroll
        for (int rh = 0; rh < 2; rh++) {
            int row = node0 + m_base + rh * 8 + r;
            if (row < NN) {
                atomicAdd(&g_asrc2[row], ps[rh]);
                atomicAdd(&g_adst2[row], pd[rh]);
            }
        }
    }
}

// layer-2 aggregation + final linear: warp per dst node, 4-wide unroll
__global__ __launch_bounds__(256) void k_agg2(const float* __restrict__ b2,
                                              const float* __restrict__ Wlin,
                                              const float* __restrict__ blin,
                                              float* __restrict__ out) {
    int w = (blockIdx.x * blockDim.x + threadIdx.x) >> 5;
    int lane = threadIdx.x & 31;
    if (w >= NN) return;
    unsigned beg = g_ptr[w], end = g_ptr[w + 1];
    float adw = g_adst2[w];
    float2 acc = make_float2(0.f, 0.f);
    float ds = 0.f;
    unsigned j = beg;
    for (; j + 4 <= end; j += 4) {
        int2 m0 = g_misc[j], m1 = g_misc[j + 1];
        int2 m2 = g_misc[j + 2], m3 = g_misc[j + 3];
        float a0 = g_asrc2[m0.x], a1 = g_asrc2[m1.x];
        float a2 = g_asrc2[m2.x], a3 = g_asrc2[m3.x];
        __half2 v0 = g_h2h[(size_t)m0.x * 32 + lane];
        __half2 v1 = g_h2h[(size_t)m1.x * 32 + lane];
        __half2 v2 = g_h2h[(size_t)m2.x * 32 + lane];
        __half2 v3 = g_h2h[(size_t)m3.x * 32 + lane];
        float al0 = __expf(lrelu(a0 + adw + __int_as_float(m0.y)));
        float al1 = __expf(lrelu(a1 + adw + __int_as_float(m1.y)));
        float al2 = __expf(lrelu(a2 + adw + __int_as_float(m2.y)));
        float al3 = __expf(lrelu(a3 + adw + __int_as_float(m3.y)));
        ds += (al0 + al1) + (al2 + al3);
        float2 f;
        f = __half22float2(v0); acc.x = fmaf(f.x, al0, acc.x); acc.y = fmaf(f.y, al0, acc.y);
        f = __half22float2(v1); acc.x = fmaf(f.x, al1, acc.x); acc.y = fmaf(f.y, al1, acc.y);
        f = __half22float2(v2); acc.x = fmaf(f.x, al2, acc.x); acc.y = fmaf(f.y, al2, acc.y);
        f = __half22float2(v3); acc.x = fmaf(f.x, al3, acc.x); acc.y = fmaf(f.y, al3, acc.y);
    }
    for (; j < end; j++) {
        int2 m0 = g_misc[j];
        float al0 = __expf(lrelu(g_asrc2[m0.x] + adw + __int_as_float(m0.y)));
        ds += al0;
        float2 f = __half22float2(g_h2h[(size_t)m0.x * 32 + lane]);
        acc.x = fmaf(f.x, al0, acc.x); acc.y = fmaf(f.y, al0, acc.y);
    }
    float inv = 1.f / (ds + 1e-16f);
    float v0 = fmaxf(acc.x * inv + b2[2 * lane], 0.f);
    float v1 = fmaxf(acc.y * inv + b2[2 * lane + 1], 0.f);
    float r = v0 * Wlin[2 * lane] + v1 * Wlin[2 * lane + 1];
#pragma unroll
    for (int o = 16; o >= 1; o >>= 1) r += __shfl_xor_sync(0xFFFFFFFFu, r, o);
    if (lane == 0) out[w] = r + blin[0];
}

// ---------------- launch ----------------
extern "C" void kernel_launch(void* const* d_in, const int* in_sizes, int n_in,
                              void* d_out, int out_size) {
    const float* x     = (const float*)d_in[0];
    const int*   ei    = (const int*)d_in[1];
    const float* eattr = (const float*)d_in[2];
    const float* W1    = (const float*)d_in[3];
    const float* We1   = (const float*)d_in[4];
    const float* as1   = (const float*)d_in[5];
    const float* ad1   = (const float*)d_in[6];
    const float* ae1   = (const float*)d_in[7];
    const float* b1    = (const float*)d_in[8];
    const float* W2    = (const float*)d_in[9];
    const float* We2   = (const float*)d_in[10];
    const float* as2   = (const float*)d_in[11];
    const float* ad2   = (const float*)d_in[12];
    const float* ae2   = (const float*)d_in[13];
    const float* b2    = (const float*)d_in[14];
    const float* Wlin  = (const float*)d_in[15];
    const float* blin  = (const float*)d_in[16];
    float* out = (float*)d_out;

    static cudaStream_t s2 = nullptr;
    static cudaEvent_t evFork = nullptr, evJoin = nullptr;
    static bool attr_done = false;
    if (!attr_done) {
        cudaFuncSetAttribute(k_gemm1, cudaFuncAttributeMaxDynamicSharedMemorySize, G1_SMEM);
        cudaFuncSetAttribute(k_gemm2, cudaFuncAttributeMaxDynamicSharedMemorySize, G2_SMEM);
        cudaStreamCreateWithFlags(&s2, cudaStreamNonBlocking);
        cudaEventCreateWithFlags(&evFork, cudaEventDisableTiming);
        cudaEventCreateWithFlags(&evJoin, cudaEventDisableTiming);
        attr_done = true;
    }

    // fork: CSR build (deg/hist/scan) on s2, concurrent with weights+gemm1
    cudaEventRecord(evFork, 0);
    cudaStreamWaitEvent(s2, evFork, 0);
    k_initdeg<<<(NN + 255) / 256, 256, 0, s2>>>();
    k_hist<<<NE / 256, 256, 0, s2>>>(ei);
    k_scan<<<1, 1024, 0, s2>>>();
    cudaEventRecord(evJoin, s2);

    k_initw<<<(NN + 255) / 256, 256>>>(We1, ae1, We2, ae2, W1, W2);
    k_gemm1<<<dim3((NN + 63) / 64, 2), 256, G1_SMEM>>>(x, as1, ad1);

    // join: edge1 needs both gemm1 results and the CSR offsets
    cudaStreamWaitEvent(0, evJoin, 0);
    k_edge1<<<(NE / 2 + 255) / 256, 256>>>(ei, eattr);
    k_agg1<<<(NN * 32 + 255) / 256, 256>>>(b1);
    k_gemm2<<<(NN + 63) / 64, 256, G2_SMEM>>>(as2, ad2);
    k_agg2<<<(NN * 32 + 255) / 256, 256>>>(b2, Wlin, blin, out);
}